// round 10
// baseline (speedup 1.0000x reference)
#include <cuda_runtime.h>
#include <cuda_bf16.h>
#include <math.h>
#include <cstdint>

#define BB   256   // batch
#define LL   1024  // enc length
#define DD   256   // ENC_D
#define HH   256   // DEC_H
#define EMBD 128
#define NOUT 172
#define KIN  640
#define NCH  16    // L / 64
#define NSM  148   // persistent grid

// ---------------- scratch (device globals; no allocation allowed) ----------
__device__ float g_A[BB * KIN];
__device__ float g_gates[BB * 4 * HH];
__device__ float g_hp[BB * DD];
__device__ float g_ctx[BB * DD];
__device__ float g_partS[BB * NCH];
__device__ float g_partC[BB * NCH * DD];
__device__ float g_logits[BB * NOUT];
__device__ uint32_t g_W1bf[256 * 132];   // W1 bf16, K-PERMUTED padded rows (528 B)

// ---------------- helpers ---------------------------------------------------
__device__ __forceinline__ float tanh_fast(float x) {
    float y;
    asm("tanh.approx.f32 %0, %1;" : "=f"(y) : "f"(x));
    return y;
}
__device__ __forceinline__ float sigmoidf(float x) {
    return 1.0f / (1.0f + expf(-x));
}
__device__ __forceinline__ void mma_bf16(float* c,
                                         uint32_t a0, uint32_t a1, uint32_t a2, uint32_t a3,
                                         uint32_t b0, uint32_t b1) {
    asm volatile(
        "mma.sync.aligned.m16n8k16.row.col.f32.bf16.bf16.f32 "
        "{%0,%1,%2,%3}, {%4,%5,%6,%7}, {%8,%9}, {%0,%1,%2,%3};"
        : "+f"(c[0]), "+f"(c[1]), "+f"(c[2]), "+f"(c[3])
        : "r"(a0), "r"(a1), "r"(a2), "r"(a3), "r"(b0), "r"(b1));
}

// attn smem layout (bytes)
#define ROWB    528                   // 264 bf16 per padded row
#define ENCBUF  33792                 // 64 x 528
#define SM_W1     0                   // 256 x 528 = 135168
#define SM_ENC0   135168
#define SM_ENC1   168960
#define SM_HP     202752              // 256 f32
#define SM_BETA   203776              // 256 f32
#define SM_WS     204800              // 64 f32
#define SM_CTX    205312              // 256 f32
#define SM_SRED   206336              // 64 x 5 f32
#define SM_TOTAL  208896

// K-pair permutation (u32 position within a row): even k ->
// pos = (k>>4)*8 + ((k&7)>>1)*2 + ((k>>3)&1)
__device__ __forceinline__ int kperm(int k) {
    return ((k >> 4) << 3) + (((k & 7) >> 1) << 1) + ((k >> 3) & 1);
}

// ---------------------------------------------------------------------------
// 1) Build LSTM input rows
// ---------------------------------------------------------------------------
__global__ void prep_A_kernel(const float* __restrict__ emb,
                              const int* __restrict__ lt,
                              const float* __restrict__ o_t,
                              const float* __restrict__ h0) {
    int b = blockIdx.x;
    int k = threadIdx.x;
    float v;
    if (k < EMBD)       v = emb[lt[b] * EMBD + k];
    else if (k < 384)   v = o_t[b * HH + (k - EMBD)];
    else                v = h0[b * HH + (k - 384)];
    g_A[b * KIN + k] = v;
}

// ---------------------------------------------------------------------------
// 1b) Pre-pack W1 -> bf16, padded rows, K-permuted
// ---------------------------------------------------------------------------
__global__ void prep_W1_kernel(const float* __restrict__ W1) {
    int n = blockIdx.x;
    int kp = threadIdx.x;
    int k = 2 * kp;
    __nv_bfloat162 h = __floats2bfloat162_rn(W1[n * DD + k], W1[n * DD + k + 1]);
    g_W1bf[n * 132 + kperm(k)] = *(uint32_t*)&h;
    if (kp < 4) g_W1bf[n * 132 + 128 + kp] = 0u;
}

// ---------------------------------------------------------------------------
// 2) gates GEMM (unchanged)
// ---------------------------------------------------------------------------
__global__ __launch_bounds__(256) void gates_gemm_kernel(
    const float* __restrict__ W_ih, const float* __restrict__ W_hh,
    const float* __restrict__ b_ih, const float* __restrict__ b_hh) {
    __shared__ float aT[32 * 65];
    __shared__ float bS[32 * 65];
    int n0 = blockIdx.x * 64;
    int m0 = blockIdx.y * 64;
    int tid = threadIdx.x;
    int tx = tid & 15, ty = tid >> 4;

    float acc[4][4];
#pragma unroll
    for (int i = 0; i < 4; i++)
#pragma unroll
        for (int j = 0; j < 4; j++) acc[i][j] = 0.f;

    for (int k0 = 0; k0 < KIN; k0 += 32) {
        __syncthreads();
#pragma unroll
        for (int rep = 0; rep < 8; rep++) {
            int idx = rep * 256 + tid;
            int r = idx >> 5, kk = idx & 31;
            aT[kk * 65 + r] = g_A[(m0 + r) * KIN + k0 + kk];
        }
#pragma unroll
        for (int rep = 0; rep < 8; rep++) {
            int idx = rep * 256 + tid;
            int j = idx >> 5, kk = idx & 31;
            int kg = k0 + kk;
            int jg = n0 + j;
            bS[kk * 65 + j] = (kg < 384) ? W_ih[jg * 384 + kg] : W_hh[jg * 256 + (kg - 384)];
        }
        __syncthreads();
#pragma unroll
        for (int kk = 0; kk < 32; kk++) {
            float a[4], w[4];
#pragma unroll
            for (int i = 0; i < 4; i++) a[i] = aT[kk * 65 + ty * 4 + i];
#pragma unroll
            for (int j = 0; j < 4; j++) w[j] = bS[kk * 65 + tx * 4 + j];
#pragma unroll
            for (int i = 0; i < 4; i++)
#pragma unroll
                for (int j = 0; j < 4; j++) acc[i][j] += a[i] * w[j];
        }
    }
#pragma unroll
    for (int i = 0; i < 4; i++) {
        int row = m0 + ty * 4 + i;
#pragma unroll
        for (int j = 0; j < 4; j++) {
            int col = n0 + tx * 4 + j;
            g_gates[row * 1024 + col] = acc[i][j] + b_ih[col] + b_hh[col];
        }
    }
}

// ---------------------------------------------------------------------------
// 3) LSTM cell
// ---------------------------------------------------------------------------
__global__ void cell_kernel(const float* __restrict__ c0, float* __restrict__ out) {
    int b = blockIdx.x, d = threadIdx.x;
    const float* g = g_gates + b * 1024;
    float ig = g[d], fg = g[256 + d], gg = g[512 + d], og = g[768 + d];
    float c = sigmoidf(fg) * c0[b * HH + d] + sigmoidf(ig) * tanhf(gg);
    float h = sigmoidf(og) * tanhf(c);
    out[b * HH + d] = h;
    out[BB * HH + b * HH + d] = c;
}

// ---------------------------------------------------------------------------
// 4) hp GEMM (unchanged)
// ---------------------------------------------------------------------------
__global__ __launch_bounds__(256) void hproj_gemm_kernel(
    const float* __restrict__ W2, const float* __restrict__ out) {
    __shared__ float aT[32 * 65];
    __shared__ float bS[32 * 65];
    int n0 = blockIdx.x * 64;
    int m0 = blockIdx.y * 64;
    int tid = threadIdx.x;
    int tx = tid & 15, ty = tid >> 4;

    float acc[4][4];
#pragma unroll
    for (int i = 0; i < 4; i++)
#pragma unroll
        for (int j = 0; j < 4; j++) acc[i][j] = 0.f;

    for (int k0 = 0; k0 < HH; k0 += 32) {
        __syncthreads();
#pragma unroll
        for (int rep = 0; rep < 8; rep++) {
            int idx = rep * 256 + tid;
            int r = idx >> 5, kk = idx & 31;
            aT[kk * 65 + r] = out[(m0 + r) * HH + k0 + kk];
        }
#pragma unroll
        for (int rep = 0; rep < 8; rep++) {
            int idx = rep * 256 + tid;
            int j = idx >> 5, kk = idx & 31;
            bS[kk * 65 + j] = W2[(n0 + j) * HH + k0 + kk];
        }
        __syncthreads();
#pragma unroll
        for (int kk = 0; kk < 32; kk++) {
            float a[4], w[4];
#pragma unroll
            for (int i = 0; i < 4; i++) a[i] = aT[kk * 65 + ty * 4 + i];
#pragma unroll
            for (int j = 0; j < 4; j++) w[j] = bS[kk * 65 + tx * 4 + j];
#pragma unroll
            for (int i = 0; i < 4; i++)
#pragma unroll
                for (int j = 0; j < 4; j++) acc[i][j] += a[i] * w[j];
        }
    }
#pragma unroll
    for (int i = 0; i < 4; i++)
#pragma unroll
        for (int j = 0; j < 4; j++)
            g_hp[(m0 + ty * 4 + i) * DD + n0 + tx * 4 + j] = acc[i][j];
}

// ---------------------------------------------------------------------------
// 5) PERSISTENT attention, software-pipelined double-buffered 64-row tiles.
//    Warp tile 32x64 (2m x 4n groups). LDG of tile t+1 issued before MMA of
//    tile t (latency hidden); convert+STS into the other buffer after MMA.
// ---------------------------------------------------------------------------
__global__ __launch_bounds__(256, 1) void attn_mma_kernel(
    const float* __restrict__ enc, const float* __restrict__ beta) {
    extern __shared__ char sm[];
    float* hpS   = (float*)(sm + SM_HP);
    float* betaS = (float*)(sm + SM_BETA);
    float* wS    = (float*)(sm + SM_WS);
    float* ctxS  = (float*)(sm + SM_CTX);
    float* sred  = (float*)(sm + SM_SRED);
    char*  w1S   = sm + SM_W1;

    int tid = threadIdx.x, wid = tid >> 5, lane = tid & 31;
    int g = lane >> 2, t = lane & 3;
    int mg = wid >> 2, ng = wid & 3;       // 2 m-groups x 4 n-groups

    // W1 bf16 (K-permuted) -> smem ONCE: 8448 uint4
    {
        const uint4* src = (const uint4*)g_W1bf;
        uint4* dst = (uint4*)w1S;
#pragma unroll 4
        for (int it = 0; it < 33; it++) dst[it * 256 + tid] = src[it * 256 + tid];
    }
    betaS[tid] = beta[tid];

    const int END = BB * NCH;
    int cur = 0;
    float4 stg[16];

    // prologue: load + stage first tile into buf0
    {
        int tl0 = blockIdx.x;
        const float* src = enc + ((size_t)(tl0 >> 4) * LL + ((tl0 & 15) << 6)) * DD;
#pragma unroll
        for (int it = 0; it < 16; it++) stg[it] = ((const float4*)src)[it * 256 + tid];
        char* sdst = sm + SM_ENC0;
#pragma unroll
        for (int it = 0; it < 16; it++) {
            int idx = it * 256 + tid;
            int r = idx >> 6, c4 = idx & 63;
            __nv_bfloat162 p0 = __floats2bfloat162_rn(stg[it].x, stg[it].y);
            __nv_bfloat162 p1 = __floats2bfloat162_rn(stg[it].z, stg[it].w);
            int k0 = 4 * c4;
            *(uint32_t*)(sdst + r * ROWB + kperm(k0) * 4)     = *(uint32_t*)&p0;
            *(uint32_t*)(sdst + r * ROWB + kperm(k0 + 2) * 4) = *(uint32_t*)&p1;
        }
    }

    for (int tl = blockIdx.x; tl < END; tl += NSM) {
        int b = tl >> 4, ch = tl & 15, l0 = ch << 6;
        const float* encB = enc + ((size_t)b * LL + l0) * DD;
        hpS[tid] = g_hp[b * DD + tid];
        __syncthreads();   // S0: buf[cur] + hpS visible

        // issue LDG for next tile (latency hidden behind MMA)
        int tn = tl + NSM;
        bool have_next = tn < END;
        if (have_next) {
            const float* srcn = enc + ((size_t)(tn >> 4) * LL + ((tn & 15) << 6)) * DD;
#pragma unroll
            for (int it = 0; it < 16; it++) stg[it] = ((const float4*)srcn)[it * 256 + tid];
        }

        // ---- MMA mainloop: warp tile rows [mg*32,+32) x cols [ng*64,+64)
        char* encS = sm + SM_ENC0 + cur * ENCBUF;
        float acc[2][8][4];
#pragma unroll
        for (int mi = 0; mi < 2; mi++)
#pragma unroll
            for (int jt = 0; jt < 8; jt++)
#pragma unroll
                for (int i = 0; i < 4; i++) acc[mi][jt][i] = 0.f;

        const char* abase = encS + (mg * 32 + g) * ROWB + t * 8;
        const char* bbase = w1S + (ng * 64 + g) * ROWB + t * 8;
#pragma unroll
        for (int kb = 0; kb < 16; kb++) {
            uint2 alo[2], ahi[2];
#pragma unroll
            for (int mi = 0; mi < 2; mi++) {
                const char* pa = abase + mi * 16 * ROWB + kb * 32;
                alo[mi] = *(const uint2*)(pa);                 // {a0, a2}
                ahi[mi] = *(const uint2*)(pa + 8 * ROWB);      // {a1, a3}
            }
#pragma unroll
            for (int jt = 0; jt < 8; jt++) {
                uint2 bf = *(const uint2*)(bbase + jt * 8 * ROWB + kb * 32);
#pragma unroll
                for (int mi = 0; mi < 2; mi++)
                    mma_bf16(acc[mi][jt], alo[mi].x, ahi[mi].x, alo[mi].y, ahi[mi].y, bf.x, bf.y);
            }
        }

        // ---- epilogue: partial scores over this warp's 64-col range
#pragma unroll
        for (int mi = 0; mi < 2; mi++) {
            float s0 = 0.f, s1 = 0.f;
#pragma unroll
            for (int jt = 0; jt < 8; jt++) {
                int c = ng * 64 + jt * 8 + t * 2;
                float b0 = betaS[c], b1 = betaS[c + 1];
                float h0v = hpS[c], h1v = hpS[c + 1];
                s0 += b0 * tanh_fast(acc[mi][jt][0] + h0v) + b1 * tanh_fast(acc[mi][jt][1] + h1v);
                s1 += b0 * tanh_fast(acc[mi][jt][2] + h0v) + b1 * tanh_fast(acc[mi][jt][3] + h1v);
            }
            s0 += __shfl_xor_sync(0xffffffffu, s0, 1);
            s0 += __shfl_xor_sync(0xffffffffu, s0, 2);
            s1 += __shfl_xor_sync(0xffffffffu, s1, 1);
            s1 += __shfl_xor_sync(0xffffffffu, s1, 2);
            if (t == 0) {
                int row = mg * 32 + mi * 16 + g;
                sred[row * 5 + ng] = s0;
                sred[(row + 8) * 5 + ng] = s1;
            }
        }
        __syncthreads();   // S1: sred complete (all MMA reads of buf done)

        if (tid < 64) {
            float s = sred[tid * 5] + sred[tid * 5 + 1] + sred[tid * 5 + 2] + sred[tid * 5 + 3];
            wS[tid] = expf(s);
        }
        __syncthreads();   // S2: wS complete

        if (tid < 32) {
            float ps = wS[tid] + wS[tid + 32];
#pragma unroll
            for (int o = 16; o > 0; o >>= 1) ps += __shfl_down_sync(0xffffffffu, ps, o);
            if (tid == 0) g_partS[b * NCH + ch] = ps;
        }

        // split context pass: group (half) handles 32 rows, fp32, float2 cols
        {
            int p = tid & 127, half = tid >> 7;
            float C0 = 0.f, C1 = 0.f;
            const float* base = encB + (half * 32) * DD + 2 * p;
            const float* wHalf = wS + half * 32;
#pragma unroll 8
            for (int r = 0; r < 32; r++) {
                float2 v = *(const float2*)(base + r * DD);
                float w = wHalf[r];
                C0 += w * v.x;
                C1 += w * v.y;
            }
            if (half) {
                ctxS[2 * p] = C0;
                ctxS[2 * p + 1] = C1;
            }
            __syncthreads();   // S3: ctxS half-1 complete
            if (!half) {
                float* dst = g_partC + (size_t)(b * NCH + ch) * DD;
                dst[2 * p] = C0 + ctxS[2 * p];
                dst[2 * p + 1] = C1 + ctxS[2 * p + 1];
            }
        }

        // ---- convert + STS next tile into the other buffer
        if (have_next) {
            char* sdst = sm + SM_ENC0 + (cur ^ 1) * ENCBUF;
#pragma unroll
            for (int it = 0; it < 16; it++) {
                int idx = it * 256 + tid;
                int r = idx >> 6, c4 = idx & 63;
                __nv_bfloat162 p0 = __floats2bfloat162_rn(stg[it].x, stg[it].y);
                __nv_bfloat162 p1 = __floats2bfloat162_rn(stg[it].z, stg[it].w);
                int k0 = 4 * c4;
                *(uint32_t*)(sdst + r * ROWB + kperm(k0) * 4)     = *(uint32_t*)&p0;
                *(uint32_t*)(sdst + r * ROWB + kperm(k0 + 2) * 4) = *(uint32_t*)&p1;
            }
        }
        cur ^= 1;
    }
}

// ---------------------------------------------------------------------------
// 6) context = sum(partC) / sum(partS)
// ---------------------------------------------------------------------------
__global__ void ctx_reduce_kernel() {
    int b = blockIdx.x, d = threadIdx.x;
    float S = 0.f, C = 0.f;
#pragma unroll
    for (int c = 0; c < NCH; c++) {
        S += g_partS[b * NCH + c];
        C += g_partC[(b * NCH + c) * DD + d];
    }
    g_ctx[b * DD + d] = C / S;
}

// ---------------------------------------------------------------------------
// 7) o_new GEMM (unchanged)
// ---------------------------------------------------------------------------
__global__ __launch_bounds__(256) void onew_gemm_kernel(
    const float* __restrict__ W3, float* __restrict__ out) {
    __shared__ float aT[32 * 65];
    __shared__ float bS[32 * 65];
    int n0 = blockIdx.x * 64;
    int m0 = blockIdx.y * 64;
    int tid = threadIdx.x;
    int tx = tid & 15, ty = tid >> 4;

    float acc[4][4];
#pragma unroll
    for (int i = 0; i < 4; i++)
#pragma unroll
        for (int j = 0; j < 4; j++) acc[i][j] = 0.f;

    for (int k0 = 0; k0 < 512; k0 += 32) {
        __syncthreads();
#pragma unroll
        for (int rep = 0; rep < 8; rep++) {
            int idx = rep * 256 + tid;
            int r = idx >> 5, kk = idx & 31;
            int kg = k0 + kk;
            aT[kk * 65 + r] = (kg < 256) ? out[(m0 + r) * HH + kg]
                                         : g_ctx[(m0 + r) * DD + (kg - 256)];
        }
#pragma unroll
        for (int rep = 0; rep < 8; rep++) {
            int idx = rep * 256 + tid;
            int j = idx >> 5, kk = idx & 31;
            bS[kk * 65 + j] = W3[(n0 + j) * 512 + k0 + kk];
        }
        __syncthreads();
#pragma unroll
        for (int kk = 0; kk < 32; kk++) {
            float a[4], w[4];
#pragma unroll
            for (int i = 0; i < 4; i++) a[i] = aT[kk * 65 + ty * 4 + i];
#pragma unroll
            for (int j = 0; j < 4; j++) w[j] = bS[kk * 65 + tx * 4 + j];
#pragma unroll
            for (int i = 0; i < 4; i++)
#pragma unroll
                for (int j = 0; j < 4; j++) acc[i][j] += a[i] * w[j];
        }
    }
#pragma unroll
    for (int i = 0; i < 4; i++)
#pragma unroll
        for (int j = 0; j < 4; j++)
            out[2 * BB * HH + (m0 + ty * 4 + i) * HH + n0 + tx * 4 + j] = tanhf(acc[i][j]);
}

// ---------------------------------------------------------------------------
// 8) logits GEMM (unchanged)
// ---------------------------------------------------------------------------
__global__ __launch_bounds__(256) void logit_gemm_kernel(
    const float* __restrict__ Wout, const float* __restrict__ out) {
    __shared__ float aT[32 * 65];
    __shared__ float bS[32 * 65];
    int n0 = blockIdx.x * 64;
    int m0 = blockIdx.y * 64;
    int tid = threadIdx.x;
    int tx = tid & 15, ty = tid >> 4;
    const float* onew = out + 2 * BB * HH;

    float acc[4][4];
#pragma unroll
    for (int i = 0; i < 4; i++)
#pragma unroll
        for (int j = 0; j < 4; j++) acc[i][j] = 0.f;

    for (int k0 = 0; k0 < HH; k0 += 32) {
        __syncthreads();
#pragma unroll
        for (int rep = 0; rep < 8; rep++) {
            int idx = rep * 256 + tid;
            int r = idx >> 5, kk = idx & 31;
            aT[kk * 65 + r] = onew[(m0 + r) * HH + k0 + kk];
        }
#pragma unroll
        for (int rep = 0; rep < 8; rep++) {
            int idx = rep * 256 + tid;
            int j = idx >> 5, kk = idx & 31;
            int jg = n0 + j;
            bS[kk * 65 + j] = (jg < NOUT) ? Wout[jg * HH + k0 + kk] : 0.f;
        }
        __syncthreads();
#pragma unroll
        for (int kk = 0; kk < 32; kk++) {
            float a[4], w[4];
#pragma unroll
            for (int i = 0; i < 4; i++) a[i] = aT[kk * 65 + ty * 4 + i];
#pragma unroll
            for (int j = 0; j < 4; j++) w[j] = bS[kk * 65 + tx * 4 + j];
#pragma unroll
            for (int i = 0; i < 4; i++)
#pragma unroll
                for (int j = 0; j < 4; j++) acc[i][j] += a[i] * w[j];
        }
    }
#pragma unroll
    for (int i = 0; i < 4; i++) {
        int row = m0 + ty * 4 + i;
#pragma unroll
        for (int j = 0; j < 4; j++) {
            int col = n0 + tx * 4 + j;
            if (col < NOUT) g_logits[row * NOUT + col] = acc[i][j];
        }
    }
}

// ---------------------------------------------------------------------------
// 9) logit softmax
// ---------------------------------------------------------------------------
__global__ void softmax_logit_kernel(float* __restrict__ out) {
    __shared__ float lg[NOUT];
    __shared__ float red;
    int b = blockIdx.x, t = threadIdx.x;
    if (t < NOUT) lg[t] = g_logits[b * NOUT + t];
    __syncthreads();
    if (t == 0) {
        float m = lg[0];
        for (int i = 1; i < NOUT; i++) m = fmaxf(m, lg[i]);
        red = m;
    }
    __syncthreads();
    float e = (t < NOUT) ? expf(lg[t] - red) : 0.f;
    __syncthreads();
    if (t < NOUT) lg[t] = e;
    __syncthreads();
    if (t == 0) {
        float s = 0.f;
        for (int i = 0; i < NOUT; i++) s += lg[i];
        red = s;
    }
    __syncthreads();
    if (t < NOUT) out[3 * BB * HH + b * NOUT + t] = lg[t] / red;
}

// ---------------------------------------------------------------------------
extern "C" void kernel_launch(void* const* d_in, const int* in_sizes, int n_in,
                              void* d_out, int out_size) {
    const float* h0      = (const float*)d_in[0];
    const float* c0      = (const float*)d_in[1];
    const float* o_t     = (const float*)d_in[2];
    const float* enc_out = (const float*)d_in[3];
    const int*   lt      = (const int*)  d_in[4];
    const float* emb     = (const float*)d_in[5];
    const float* W_ih    = (const float*)d_in[6];
    const float* W_hh    = (const float*)d_in[7];
    const float* b_ih    = (const float*)d_in[8];
    const float* b_hh    = (const float*)d_in[9];
    const float* W1      = (const float*)d_in[10];
    const float* W2      = (const float*)d_in[11];
    const float* W3      = (const float*)d_in[12];
    const float* W_out   = (const float*)d_in[13];
    const float* beta    = (const float*)d_in[14];
    float* out = (float*)d_out;

    cudaFuncSetAttribute(attn_mma_kernel, cudaFuncAttributeMaxDynamicSharedMemorySize, SM_TOTAL);

    prep_A_kernel<<<BB, KIN>>>(emb, lt, o_t, h0);
    prep_W1_kernel<<<256, 128>>>(W1);
    gates_gemm_kernel<<<dim3(16, 4), 256>>>(W_ih, W_hh, b_ih, b_hh);
    cell_kernel<<<BB, HH>>>(c0, out);
    hproj_gemm_kernel<<<dim3(4, 4), 256>>>(W2, out);
    attn_mma_kernel<<<NSM, 256, SM_TOTAL>>>(enc_out, beta);
    ctx_reduce_kernel<<<BB, DD>>>();
    onew_gemm_kernel<<<dim3(4, 4), 256>>>(W3, out);
    logit_gemm_kernel<<<dim3(3, 4), 256>>>(W_out, out);
    softmax_logit_kernel<<<BB, 192>>>(out);
}

// round 11
// speedup vs baseline: 1.0577x; 1.0577x over previous
#include <cuda_runtime.h>
#include <cuda_bf16.h>
#include <math.h>
#include <cstdint>

#define BB   256   // batch
#define LL   1024  // enc length
#define DD   256   // ENC_D
#define HH   256   // DEC_H
#define EMBD 128
#define NOUT 172
#define KIN  640
#define NCH  8     // L / 128
#define NSM  148   // persistent grid

// ---------------- scratch (device globals; no allocation allowed) ----------
__device__ float g_A[BB * KIN];
__device__ float g_gates[BB * 4 * HH];
__device__ float g_hp[BB * DD];
__device__ float g_ctx[BB * DD];
__device__ float g_partS[BB * NCH];
__device__ float g_partC[BB * NCH * DD];
__device__ float g_logits[BB * NOUT];
__device__ uint32_t g_W1bf[256 * 136];   // W1 bf16, K-PERMUTED rows of 136 u32 (544 B)

// ---------------- helpers ---------------------------------------------------
__device__ __forceinline__ float tanh_fast(float x) {
    float y;
    asm("tanh.approx.f32 %0, %1;" : "=f"(y) : "f"(x));
    return y;
}
__device__ __forceinline__ float sigmoidf(float x) {
    return 1.0f / (1.0f + expf(-x));
}
__device__ __forceinline__ void mma_bf16(float* c,
                                         uint32_t a0, uint32_t a1, uint32_t a2, uint32_t a3,
                                         uint32_t b0, uint32_t b1) {
    asm volatile(
        "mma.sync.aligned.m16n8k16.row.col.f32.bf16.bf16.f32 "
        "{%0,%1,%2,%3}, {%4,%5,%6,%7}, {%8,%9}, {%0,%1,%2,%3};"
        : "+f"(c[0]), "+f"(c[1]), "+f"(c[2]), "+f"(c[3])
        : "r"(a0), "r"(a1), "r"(a2), "r"(a3), "r"(b0), "r"(b1));
}

// attn smem layout (bytes) — ROWB 544 = 136 u32: 8-bank row shift, conflict-free
#define ROWB    544
#define SM_W1     0                   // 256 x 544 = 139264
#define SM_ENC    139264              // 128 x 544 = 69632
#define SM_HP     208896              // 256 f32
#define SM_BETA   209920              // 256 f32
#define SM_WS     210944              // 128 f32
#define SM_CTX    211456              // 256 f32
#define SM_SRED   212480              // 128 x 5 f32 = 2560
#define SM_TOTAL  215040

// K-pair permutation (u32 position within a row): even k ->
// pos = (k>>4)*8 + ((k&7)>>1)*2 + ((k>>3)&1)
__device__ __forceinline__ int kperm(int k) {
    return ((k >> 4) << 3) + (((k & 7) >> 1) << 1) + ((k >> 3) & 1);
}

// ---------------------------------------------------------------------------
// 1) Build LSTM input rows
// ---------------------------------------------------------------------------
__global__ void prep_A_kernel(const float* __restrict__ emb,
                              const int* __restrict__ lt,
                              const float* __restrict__ o_t,
                              const float* __restrict__ h0) {
    int b = blockIdx.x;
    int k = threadIdx.x;
    float v;
    if (k < EMBD)       v = emb[lt[b] * EMBD + k];
    else if (k < 384)   v = o_t[b * HH + (k - EMBD)];
    else                v = h0[b * HH + (k - 384)];
    g_A[b * KIN + k] = v;
}

// ---------------------------------------------------------------------------
// 1b) Pre-pack W1 -> bf16, 136-u32 rows, K-permuted
// ---------------------------------------------------------------------------
__global__ void prep_W1_kernel(const float* __restrict__ W1) {
    int n = blockIdx.x;           // 256 rows
    int kp = threadIdx.x;         // 128 pairs
    int k = 2 * kp;
    __nv_bfloat162 h = __floats2bfloat162_rn(W1[n * DD + k], W1[n * DD + k + 1]);
    g_W1bf[n * 136 + kperm(k)] = *(uint32_t*)&h;
    if (kp < 8) g_W1bf[n * 136 + 128 + kp] = 0u;   // zero 8-u32 padding
}

// ---------------------------------------------------------------------------
// 2) gates GEMM (unchanged)
// ---------------------------------------------------------------------------
__global__ __launch_bounds__(256) void gates_gemm_kernel(
    const float* __restrict__ W_ih, const float* __restrict__ W_hh,
    const float* __restrict__ b_ih, const float* __restrict__ b_hh) {
    __shared__ float aT[32 * 65];
    __shared__ float bS[32 * 65];
    int n0 = blockIdx.x * 64;
    int m0 = blockIdx.y * 64;
    int tid = threadIdx.x;
    int tx = tid & 15, ty = tid >> 4;

    float acc[4][4];
#pragma unroll
    for (int i = 0; i < 4; i++)
#pragma unroll
        for (int j = 0; j < 4; j++) acc[i][j] = 0.f;

    for (int k0 = 0; k0 < KIN; k0 += 32) {
        __syncthreads();
#pragma unroll
        for (int rep = 0; rep < 8; rep++) {
            int idx = rep * 256 + tid;
            int r = idx >> 5, kk = idx & 31;
            aT[kk * 65 + r] = g_A[(m0 + r) * KIN + k0 + kk];
        }
#pragma unroll
        for (int rep = 0; rep < 8; rep++) {
            int idx = rep * 256 + tid;
            int j = idx >> 5, kk = idx & 31;
            int kg = k0 + kk;
            int jg = n0 + j;
            bS[kk * 65 + j] = (kg < 384) ? W_ih[jg * 384 + kg] : W_hh[jg * 256 + (kg - 384)];
        }
        __syncthreads();
#pragma unroll
        for (int kk = 0; kk < 32; kk++) {
            float a[4], w[4];
#pragma unroll
            for (int i = 0; i < 4; i++) a[i] = aT[kk * 65 + ty * 4 + i];
#pragma unroll
            for (int j = 0; j < 4; j++) w[j] = bS[kk * 65 + tx * 4 + j];
#pragma unroll
            for (int i = 0; i < 4; i++)
#pragma unroll
                for (int j = 0; j < 4; j++) acc[i][j] += a[i] * w[j];
        }
    }
#pragma unroll
    for (int i = 0; i < 4; i++) {
        int row = m0 + ty * 4 + i;
#pragma unroll
        for (int j = 0; j < 4; j++) {
            int col = n0 + tx * 4 + j;
            g_gates[row * 1024 + col] = acc[i][j] + b_ih[col] + b_hh[col];
        }
    }
}

// ---------------------------------------------------------------------------
// 3) LSTM cell
// ---------------------------------------------------------------------------
__global__ void cell_kernel(const float* __restrict__ c0, float* __restrict__ out) {
    int b = blockIdx.x, d = threadIdx.x;
    const float* g = g_gates + b * 1024;
    float ig = g[d], fg = g[256 + d], gg = g[512 + d], og = g[768 + d];
    float c = sigmoidf(fg) * c0[b * HH + d] + sigmoidf(ig) * tanhf(gg);
    float h = sigmoidf(og) * tanhf(c);
    out[b * HH + d] = h;
    out[BB * HH + b * HH + d] = c;
}

// ---------------------------------------------------------------------------
// 4) hp GEMM (unchanged)
// ---------------------------------------------------------------------------
__global__ __launch_bounds__(256) void hproj_gemm_kernel(
    const float* __restrict__ W2, const float* __restrict__ out) {
    __shared__ float aT[32 * 65];
    __shared__ float bS[32 * 65];
    int n0 = blockIdx.x * 64;
    int m0 = blockIdx.y * 64;
    int tid = threadIdx.x;
    int tx = tid & 15, ty = tid >> 4;

    float acc[4][4];
#pragma unroll
    for (int i = 0; i < 4; i++)
#pragma unroll
        for (int j = 0; j < 4; j++) acc[i][j] = 0.f;

    for (int k0 = 0; k0 < HH; k0 += 32) {
        __syncthreads();
#pragma unroll
        for (int rep = 0; rep < 8; rep++) {
            int idx = rep * 256 + tid;
            int r = idx >> 5, kk = idx & 31;
            aT[kk * 65 + r] = out[(m0 + r) * HH + k0 + kk];
        }
#pragma unroll
        for (int rep = 0; rep < 8; rep++) {
            int idx = rep * 256 + tid;
            int j = idx >> 5, kk = idx & 31;
            bS[kk * 65 + j] = W2[(n0 + j) * HH + k0 + kk];
        }
        __syncthreads();
#pragma unroll
        for (int kk = 0; kk < 32; kk++) {
            float a[4], w[4];
#pragma unroll
            for (int i = 0; i < 4; i++) a[i] = aT[kk * 65 + ty * 4 + i];
#pragma unroll
            for (int j = 0; j < 4; j++) w[j] = bS[kk * 65 + tx * 4 + j];
#pragma unroll
            for (int i = 0; i < 4; i++)
#pragma unroll
                for (int j = 0; j < 4; j++) acc[i][j] += a[i] * w[j];
        }
    }
#pragma unroll
    for (int i = 0; i < 4; i++)
#pragma unroll
        for (int j = 0; j < 4; j++)
            g_hp[(m0 + ty * 4 + i) * DD + n0 + tx * 4 + j] = acc[i][j];
}

// ---------------------------------------------------------------------------
// 5) PERSISTENT attention (HMMA bf16), 64x64 warp tiles, 128-row l-tiles,
//    conflict-free ROWB=544 SMEM. (R9 structure + bank-conflict fix.)
// ---------------------------------------------------------------------------
__global__ __launch_bounds__(256) void attn_mma_kernel(
    const float* __restrict__ enc, const float* __restrict__ beta) {
    extern __shared__ char sm[];
    float* hpS   = (float*)(sm + SM_HP);
    float* betaS = (float*)(sm + SM_BETA);
    float* wS    = (float*)(sm + SM_WS);
    float* ctxS  = (float*)(sm + SM_CTX);
    float* sred  = (float*)(sm + SM_SRED);
    char*  encS  = sm + SM_ENC;
    char*  w1S   = sm + SM_W1;

    int tid = threadIdx.x, wid = tid >> 5, lane = tid & 31;
    int g = lane >> 2, t = lane & 3;
    int mg = wid >> 2, ng = wid & 3;       // 2 m-groups x 4 n-groups
    int stage_m0 = wid * 16;               // staging rows owned by this warp

    // W1 bf16 (K-permuted, 136-u32 rows) -> smem ONCE: 8704 uint4 = 34 x 256
    {
        const uint4* src = (const uint4*)g_W1bf;
        uint4* dst = (uint4*)w1S;
#pragma unroll 4
        for (int it = 0; it < 34; it++) dst[it * 256 + tid] = src[it * 256 + tid];
    }
    betaS[tid] = beta[tid];
    __syncthreads();

    for (int tl = blockIdx.x; tl < BB * NCH; tl += NSM) {
        int b = tl >> 3, ch = tl & 7, l0 = ch << 7;
        const float* encB = enc + ((size_t)b * LL + l0) * DD;

        hpS[tid] = g_hp[b * DD + tid];

        // per-warp enc staging: rows [stage_m0, +16) fp32 -> bf16 K-permuted smem
        {
            const float* wrow = encB + stage_m0 * DD;
            char* sdst = encS + stage_m0 * ROWB;
#pragma unroll 8
            for (int it = 0; it < 32; it++) {
                int idx = it * 32 + lane;       // 1024 float4 per warp
                int rl = idx >> 6;
                int c4 = idx & 63;
                float4 v = *(const float4*)(wrow + rl * DD + c4 * 4);
                __nv_bfloat162 p0 = __floats2bfloat162_rn(v.x, v.y);
                __nv_bfloat162 p1 = __floats2bfloat162_rn(v.z, v.w);
                int k0 = 4 * c4;
                *(uint32_t*)(sdst + rl * ROWB + kperm(k0) * 4)     = *(uint32_t*)&p0;
                *(uint32_t*)(sdst + rl * ROWB + kperm(k0 + 2) * 4) = *(uint32_t*)&p1;
            }
        }
        __syncthreads();   // S0: enc tile + hp complete

        // ---- MMA mainloop: warp tile rows [mg*64,+64) x cols [ng*64,+64)
        float acc[4][8][4];
#pragma unroll
        for (int mi = 0; mi < 4; mi++)
#pragma unroll
            for (int jt = 0; jt < 8; jt++)
#pragma unroll
                for (int i = 0; i < 4; i++) acc[mi][jt][i] = 0.f;

        const char* abase = encS + (mg * 64 + g) * ROWB + t * 8;
        const char* bbase = w1S + (ng * 64 + g) * ROWB + t * 8;
#pragma unroll
        for (int kb = 0; kb < 16; kb++) {
            uint2 alo[4], ahi[4];
#pragma unroll
            for (int mi = 0; mi < 4; mi++) {
                const char* pa = abase + mi * 16 * ROWB + kb * 32;
                alo[mi] = *(const uint2*)(pa);                 // {a0, a2}
                ahi[mi] = *(const uint2*)(pa + 8 * ROWB);      // {a1, a3}
            }
#pragma unroll
            for (int jt = 0; jt < 8; jt++) {
                uint2 bf = *(const uint2*)(bbase + jt * 8 * ROWB + kb * 32);
#pragma unroll
                for (int mi = 0; mi < 4; mi++)
                    mma_bf16(acc[mi][jt], alo[mi].x, ahi[mi].x, alo[mi].y, ahi[mi].y, bf.x, bf.y);
            }
        }

        // ---- epilogue: partial scores over this warp's 64-col range
#pragma unroll
        for (int mi = 0; mi < 4; mi++) {
            float s0 = 0.f, s1 = 0.f;
#pragma unroll
            for (int jt = 0; jt < 8; jt++) {
                int c = ng * 64 + jt * 8 + t * 2;
                float b0 = betaS[c], b1 = betaS[c + 1];
                float h0v = hpS[c], h1v = hpS[c + 1];
                s0 += b0 * tanh_fast(acc[mi][jt][0] + h0v) + b1 * tanh_fast(acc[mi][jt][1] + h1v);
                s1 += b0 * tanh_fast(acc[mi][jt][2] + h0v) + b1 * tanh_fast(acc[mi][jt][3] + h1v);
            }
            s0 += __shfl_xor_sync(0xffffffffu, s0, 1);
            s0 += __shfl_xor_sync(0xffffffffu, s0, 2);
            s1 += __shfl_xor_sync(0xffffffffu, s1, 1);
            s1 += __shfl_xor_sync(0xffffffffu, s1, 2);
            if (t == 0) {
                int row = mg * 64 + mi * 16 + g;
                sred[row * 5 + ng] = s0;
                sred[(row + 8) * 5 + ng] = s1;
            }
        }
        __syncthreads();   // S1: sred complete

        if (tid < 128) {
            float s = sred[tid * 5] + sred[tid * 5 + 1] + sred[tid * 5 + 2] + sred[tid * 5 + 3];
            wS[tid] = expf(s);
        }
        __syncthreads();   // S2: wS complete

        if (tid < 32) {
            float ps = wS[tid] + wS[tid + 32] + wS[tid + 64] + wS[tid + 96];
#pragma unroll
            for (int o = 16; o > 0; o >>= 1) ps += __shfl_down_sync(0xffffffffu, ps, o);
            if (tid == 0) g_partS[b * NCH + ch] = ps;
        }

        // split context pass: group (half) handles 64 rows, fp32, float2 cols
        {
            int p = tid & 127, half = tid >> 7;
            float C0 = 0.f, C1 = 0.f;
            const float* base = encB + (half * 64) * DD + 2 * p;
            const float* wHalf = wS + half * 64;
#pragma unroll 8
            for (int r = 0; r < 64; r++) {
                float2 v = *(const float2*)(base + r * DD);
                float w = wHalf[r];
                C0 += w * v.x;
                C1 += w * v.y;
            }
            if (half) {
                ctxS[2 * p] = C0;
                ctxS[2 * p + 1] = C1;
            }
            __syncthreads();   // S3: ctxS half-1 complete
            if (!half) {
                float* dst = g_partC + (size_t)(b * NCH + ch) * DD;
                dst[2 * p] = C0 + ctxS[2 * p];
                dst[2 * p + 1] = C1 + ctxS[2 * p + 1];
            }
        }
        __syncthreads();   // S4: protect smem before next tile
    }
}

// ---------------------------------------------------------------------------
// 6) context = sum(partC) / sum(partS)
// ---------------------------------------------------------------------------
__global__ void ctx_reduce_kernel() {
    int b = blockIdx.x, d = threadIdx.x;
    float S = 0.f, C = 0.f;
#pragma unroll
    for (int c = 0; c < NCH; c++) {
        S += g_partS[b * NCH + c];
        C += g_partC[(b * NCH + c) * DD + d];
    }
    g_ctx[b * DD + d] = C / S;
}

// ---------------------------------------------------------------------------
// 7) o_new GEMM (unchanged)
// ---------------------------------------------------------------------------
__global__ __launch_bounds__(256) void onew_gemm_kernel(
    const float* __restrict__ W3, float* __restrict__ out) {
    __shared__ float aT[32 * 65];
    __shared__ float bS[32 * 65];
    int n0 = blockIdx.x * 64;
    int m0 = blockIdx.y * 64;
    int tid = threadIdx.x;
    int tx = tid & 15, ty = tid >> 4;

    float acc[4][4];
#pragma unroll
    for (int i = 0; i < 4; i++)
#pragma unroll
        for (int j = 0; j < 4; j++) acc[i][j] = 0.f;

    for (int k0 = 0; k0 < 512; k0 += 32) {
        __syncthreads();
#pragma unroll
        for (int rep = 0; rep < 8; rep++) {
            int idx = rep * 256 + tid;
            int r = idx >> 5, kk = idx & 31;
            int kg = k0 + kk;
            aT[kk * 65 + r] = (kg < 256) ? out[(m0 + r) * HH + kg]
                                         : g_ctx[(m0 + r) * DD + (kg - 256)];
        }
#pragma unroll
        for (int rep = 0; rep < 8; rep++) {
            int idx = rep * 256 + tid;
            int j = idx >> 5, kk = idx & 31;
            bS[kk * 65 + j] = W3[(n0 + j) * 512 + k0 + kk];
        }
        __syncthreads();
#pragma unroll
        for (int kk = 0; kk < 32; kk++) {
            float a[4], w[4];
#pragma unroll
            for (int i = 0; i < 4; i++) a[i] = aT[kk * 65 + ty * 4 + i];
#pragma unroll
            for (int j = 0; j < 4; j++) w[j] = bS[kk * 65 + tx * 4 + j];
#pragma unroll
            for (int i = 0; i < 4; i++)
#pragma unroll
                for (int j = 0; j < 4; j++) acc[i][j] += a[i] * w[j];
        }
    }
#pragma unroll
    for (int i = 0; i < 4; i++)
#pragma unroll
        for (int j = 0; j < 4; j++)
            out[2 * BB * HH + (m0 + ty * 4 + i) * HH + n0 + tx * 4 + j] = tanhf(acc[i][j]);
}

// ---------------------------------------------------------------------------
// 8) logits GEMM (unchanged)
// ---------------------------------------------------------------------------
__global__ __launch_bounds__(256) void logit_gemm_kernel(
    const float* __restrict__ Wout, const float* __restrict__ out) {
    __shared__ float aT[32 * 65];
    __shared__ float bS[32 * 65];
    int n0 = blockIdx.x * 64;
    int m0 = blockIdx.y * 64;
    int tid = threadIdx.x;
    int tx = tid & 15, ty = tid >> 4;
    const float* onew = out + 2 * BB * HH;

    float acc[4][4];
#pragma unroll
    for (int i = 0; i < 4; i++)
#pragma unroll
        for (int j = 0; j < 4; j++) acc[i][j] = 0.f;

    for (int k0 = 0; k0 < HH; k0 += 32) {
        __syncthreads();
#pragma unroll
        for (int rep = 0; rep < 8; rep++) {
            int idx = rep * 256 + tid;
            int r = idx >> 5, kk = idx & 31;
            aT[kk * 65 + r] = onew[(m0 + r) * HH + k0 + kk];
        }
#pragma unroll
        for (int rep = 0; rep < 8; rep++) {
            int idx = rep * 256 + tid;
            int j = idx >> 5, kk = idx & 31;
            int jg = n0 + j;
            bS[kk * 65 + j] = (jg < NOUT) ? Wout[jg * HH + k0 + kk] : 0.f;
        }
        __syncthreads();
#pragma unroll
        for (int kk = 0; kk < 32; kk++) {
            float a[4], w[4];
#pragma unroll
            for (int i = 0; i < 4; i++) a[i] = aT[kk * 65 + ty * 4 + i];
#pragma unroll
            for (int j = 0; j < 4; j++) w[j] = bS[kk * 65 + tx * 4 + j];
#pragma unroll
            for (int i = 0; i < 4; i++)
#pragma unroll
                for (int j = 0; j < 4; j++) acc[i][j] += a[i] * w[j];
        }
    }
#pragma unroll
    for (int i = 0; i < 4; i++) {
        int row = m0 + ty * 4 + i;
#pragma unroll
        for (int j = 0; j < 4; j++) {
            int col = n0 + tx * 4 + j;
            if (col < NOUT) g_logits[row * NOUT + col] = acc[i][j];
        }
    }
}

// ---------------------------------------------------------------------------
// 9) logit softmax
// ---------------------------------------------------------------------------
__global__ void softmax_logit_kernel(float* __restrict__ out) {
    __shared__ float lg[NOUT];
    __shared__ float red;
    int b = blockIdx.x, t = threadIdx.x;
    if (t < NOUT) lg[t] = g_logits[b * NOUT + t];
    __syncthreads();
    if (t == 0) {
        float m = lg[0];
        for (int i = 1; i < NOUT; i++) m = fmaxf(m, lg[i]);
        red = m;
    }
    __syncthreads();
    float e = (t < NOUT) ? expf(lg[t] - red) : 0.f;
    __syncthreads();
    if (t < NOUT) lg[t] = e;
    __syncthreads();
    if (t == 0) {
        float s = 0.f;
        for (int i = 0; i < NOUT; i++) s += lg[i];
        red = s;
    }
    __syncthreads();
    if (t < NOUT) out[3 * BB * HH + b * NOUT + t] = lg[t] / red;
}

// ---------------------------------------------------------------------------
extern "C" void kernel_launch(void* const* d_in, const int* in_sizes, int n_in,
                              void* d_out, int out_size) {
    const float* h0      = (const float*)d_in[0];
    const float* c0      = (const float*)d_in[1];
    const float* o_t     = (const float*)d_in[2];
    const float* enc_out = (const float*)d_in[3];
    const int*   lt      = (const int*)  d_in[4];
    const float* emb     = (const float*)d_in[5];
    const float* W_ih    = (const float*)d_in[6];
    const float* W_hh    = (const float*)d_in[7];
    const float* b_ih    = (const float*)d_in[8];
    const float* b_hh    = (const float*)d_in[9];
    const float* W1      = (const float*)d_in[10];
    const float* W2      = (const float*)d_in[11];
    const float* W3      = (const float*)d_in[12];
    const float* W_out   = (const float*)d_in[13];
    const float* beta    = (const float*)d_in[14];
    float* out = (float*)d_out;

    cudaFuncSetAttribute(attn_mma_kernel, cudaFuncAttributeMaxDynamicSharedMemorySize, SM_TOTAL);

    prep_A_kernel<<<BB, KIN>>>(emb, lt, o_t, h0);
    prep_W1_kernel<<<256, 128>>>(W1);
    gates_gemm_kernel<<<dim3(16, 4), 256>>>(W_ih, W_hh, b_ih, b_hh);
    cell_kernel<<<BB, HH>>>(c0, out);
    hproj_gemm_kernel<<<dim3(4, 4), 256>>>(W2, out);
    attn_mma_kernel<<<NSM, 256, SM_TOTAL>>>(enc_out, beta);
    ctx_reduce_kernel<<<BB, DD>>>();
    onew_gemm_kernel<<<dim3(4, 4), 256>>>(W3, out);
    logit_gemm_kernel<<<dim3(3, 4), 256>>>(W_out, out);
    softmax_logit_kernel<<<BB, 192>>>(out);
}

// round 12
// speedup vs baseline: 1.0696x; 1.0113x over previous
#include <cuda_runtime.h>
#include <cuda_bf16.h>
#include <math.h>
#include <cstdint>

#define BB   256
#define LL   1024
#define DD   256
#define HH   256
#define EMBD 128
#define NOUT 172
#define KIN  640
#define NCH  8     // L / 128
#define NSM  148

// ---------------- scratch (device globals; no allocation allowed) ----------
__device__ float g_A[BB * KIN];
__device__ float g_gates[BB * 4 * HH];
__device__ float g_hp[BB * DD];
__device__ float g_ctx[BB * DD];
__device__ float g_partS[BB * NCH];
__device__ float g_partC[BB * NCH * 2 * DD];   // two half-partials per tile
__device__ float g_logits[BB * NOUT];
__device__ uint32_t g_W1bf[256 * 136];   // W1 bf16, K-PERMUTED rows of 136 u32 (544 B)

// ---------------- helpers ---------------------------------------------------
__device__ __forceinline__ float tanh_fast(float x) {
    float y;
    asm("tanh.approx.f32 %0, %1;" : "=f"(y) : "f"(x));
    return y;
}
__device__ __forceinline__ float sigmoidf(float x) {
    return 1.0f / (1.0f + expf(-x));
}
__device__ __forceinline__ void mma_bf16(float* c,
                                         uint32_t a0, uint32_t a1, uint32_t a2, uint32_t a3,
                                         uint32_t b0, uint32_t b1) {
    asm volatile(
        "mma.sync.aligned.m16n8k16.row.col.f32.bf16.bf16.f32 "
        "{%0,%1,%2,%3}, {%4,%5,%6,%7}, {%8,%9}, {%0,%1,%2,%3};"
        : "+f"(c[0]), "+f"(c[1]), "+f"(c[2]), "+f"(c[3])
        : "r"(a0), "r"(a1), "r"(a2), "r"(a3), "r"(b0), "r"(b1));
}
__device__ __forceinline__ void named_bar(int id) {
    asm volatile("bar.sync %0, %1;" :: "r"(id), "r"(128) : "memory");
}

// attn smem layout (bytes) — ROWB 544 = 136 u32 (8-bank row shift, conflict-free)
#define ROWB    544
#define SM_W1     0                   // 256 x 544 = 139264
#define SM_ENC    139264              // 128 x 544 = 69632
#define SM_HP     208896              // 2 x 256 f32 (per-half copies) = 2048
#define SM_BETA   210944              // 256 f32
#define SM_WS     211968              // 128 f32
#define SM_SRED   212480              // 128 x 5 f32 = 2560
#define SM_TOTAL  215040

// K-pair permutation: even k -> pos = (k>>4)*8 + ((k&7)>>1)*2 + ((k>>3)&1)
__device__ __forceinline__ int kperm(int k) {
    return ((k >> 4) << 3) + (((k & 7) >> 1) << 1) + ((k >> 3) & 1);
}

// ---------------------------------------------------------------------------
// 1) Build LSTM input rows
// ---------------------------------------------------------------------------
__global__ void prep_A_kernel(const float* __restrict__ emb,
                              const int* __restrict__ lt,
                              const float* __restrict__ o_t,
                              const float* __restrict__ h0) {
    int b = blockIdx.x;
    int k = threadIdx.x;
    float v;
    if (k < EMBD)       v = emb[lt[b] * EMBD + k];
    else if (k < 384)   v = o_t[b * HH + (k - EMBD)];
    else                v = h0[b * HH + (k - 384)];
    g_A[b * KIN + k] = v;
}

// ---------------------------------------------------------------------------
// 1b) Pre-pack W1 -> bf16, 136-u32 rows, K-permuted
// ---------------------------------------------------------------------------
__global__ void prep_W1_kernel(const float* __restrict__ W1) {
    int n = blockIdx.x;
    int kp = threadIdx.x;
    int k = 2 * kp;
    __nv_bfloat162 h = __floats2bfloat162_rn(W1[n * DD + k], W1[n * DD + k + 1]);
    g_W1bf[n * 136 + kperm(k)] = *(uint32_t*)&h;
    if (kp < 8) g_W1bf[n * 136 + 128 + kp] = 0u;
}

// ---------------------------------------------------------------------------
// 2) gates GEMM (unchanged)
// ---------------------------------------------------------------------------
__global__ __launch_bounds__(256) void gates_gemm_kernel(
    const float* __restrict__ W_ih, const float* __restrict__ W_hh,
    const float* __restrict__ b_ih, const float* __restrict__ b_hh) {
    __shared__ float aT[32 * 65];
    __shared__ float bS[32 * 65];
    int n0 = blockIdx.x * 64;
    int m0 = blockIdx.y * 64;
    int tid = threadIdx.x;
    int tx = tid & 15, ty = tid >> 4;

    float acc[4][4];
#pragma unroll
    for (int i = 0; i < 4; i++)
#pragma unroll
        for (int j = 0; j < 4; j++) acc[i][j] = 0.f;

    for (int k0 = 0; k0 < KIN; k0 += 32) {
        __syncthreads();
#pragma unroll
        for (int rep = 0; rep < 8; rep++) {
            int idx = rep * 256 + tid;
            int r = idx >> 5, kk = idx & 31;
            aT[kk * 65 + r] = g_A[(m0 + r) * KIN + k0 + kk];
        }
#pragma unroll
        for (int rep = 0; rep < 8; rep++) {
            int idx = rep * 256 + tid;
            int j = idx >> 5, kk = idx & 31;
            int kg = k0 + kk;
            int jg = n0 + j;
            bS[kk * 65 + j] = (kg < 384) ? W_ih[jg * 384 + kg] : W_hh[jg * 256 + (kg - 384)];
        }
        __syncthreads();
#pragma unroll
        for (int kk = 0; kk < 32; kk++) {
            float a[4], w[4];
#pragma unroll
            for (int i = 0; i < 4; i++) a[i] = aT[kk * 65 + ty * 4 + i];
#pragma unroll
            for (int j = 0; j < 4; j++) w[j] = bS[kk * 65 + tx * 4 + j];
#pragma unroll
            for (int i = 0; i < 4; i++)
#pragma unroll
                for (int j = 0; j < 4; j++) acc[i][j] += a[i] * w[j];
        }
    }
#pragma unroll
    for (int i = 0; i < 4; i++) {
        int row = m0 + ty * 4 + i;
#pragma unroll
        for (int j = 0; j < 4; j++) {
            int col = n0 + tx * 4 + j;
            g_gates[row * 1024 + col] = acc[i][j] + b_ih[col] + b_hh[col];
        }
    }
}

// ---------------------------------------------------------------------------
// 3) LSTM cell
// ---------------------------------------------------------------------------
__global__ void cell_kernel(const float* __restrict__ c0, float* __restrict__ out) {
    int b = blockIdx.x, d = threadIdx.x;
    const float* g = g_gates + b * 1024;
    float ig = g[d], fg = g[256 + d], gg = g[512 + d], og = g[768 + d];
    float c = sigmoidf(fg) * c0[b * HH + d] + sigmoidf(ig) * tanhf(gg);
    float h = sigmoidf(og) * tanhf(c);
    out[b * HH + d] = h;
    out[BB * HH + b * HH + d] = c;
}

// ---------------------------------------------------------------------------
// 4) hp GEMM (unchanged)
// ---------------------------------------------------------------------------
__global__ __launch_bounds__(256) void hproj_gemm_kernel(
    const float* __restrict__ W2, const float* __restrict__ out) {
    __shared__ float aT[32 * 65];
    __shared__ float bS[32 * 65];
    int n0 = blockIdx.x * 64;
    int m0 = blockIdx.y * 64;
    int tid = threadIdx.x;
    int tx = tid & 15, ty = tid >> 4;

    float acc[4][4];
#pragma unroll
    for (int i = 0; i < 4; i++)
#pragma unroll
        for (int j = 0; j < 4; j++) acc[i][j] = 0.f;

    for (int k0 = 0; k0 < HH; k0 += 32) {
        __syncthreads();
#pragma unroll
        for (int rep = 0; rep < 8; rep++) {
            int idx = rep * 256 + tid;
            int r = idx >> 5, kk = idx & 31;
            aT[kk * 65 + r] = out[(m0 + r) * HH + k0 + kk];
        }
#pragma unroll
        for (int rep = 0; rep < 8; rep++) {
            int idx = rep * 256 + tid;
            int j = idx >> 5, kk = idx & 31;
            bS[kk * 65 + j] = W2[(n0 + j) * HH + k0 + kk];
        }
        __syncthreads();
#pragma unroll
        for (int kk = 0; kk < 32; kk++) {
            float a[4], w[4];
#pragma unroll
            for (int i = 0; i < 4; i++) a[i] = aT[kk * 65 + ty * 4 + i];
#pragma unroll
            for (int j = 0; j < 4; j++) w[j] = bS[kk * 65 + tx * 4 + j];
#pragma unroll
            for (int i = 0; i < 4; i++)
#pragma unroll
                for (int j = 0; j < 4; j++) acc[i][j] += a[i] * w[j];
        }
    }
#pragma unroll
    for (int i = 0; i < 4; i++)
#pragma unroll
        for (int j = 0; j < 4; j++)
            g_hp[(m0 + ty * 4 + i) * DD + n0 + tx * 4 + j] = acc[i][j];
}

// ---------------------------------------------------------------------------
// 5) PERSISTENT attention, fused tail phase + half-block named barriers.
//    Each half (warps 0-3 / 4-7) stages + consumes its own 64 enc rows.
// ---------------------------------------------------------------------------
__global__ __launch_bounds__(256) void attn_mma_kernel(
    const float* __restrict__ enc, const float* __restrict__ beta) {
    extern __shared__ char sm[];
    float* hpS   = (float*)(sm + SM_HP);     // [2][256]
    float* betaS = (float*)(sm + SM_BETA);
    float* wS    = (float*)(sm + SM_WS);
    float* sred  = (float*)(sm + SM_SRED);
    char*  encS  = sm + SM_ENC;
    char*  w1S   = sm + SM_W1;

    int tid = threadIdx.x, wid = tid >> 5, lane = tid & 31;
    int g = lane >> 2, t = lane & 3;
    int mg = wid >> 2, ng = wid & 3;
    int half = mg;                         // warps 0-3: half 0; 4-7: half 1
    int p = tid & 127;                     // id within half
    int stage_m0 = wid * 16;
    float* hpMy = hpS + half * 256;

    // W1 bf16 (K-permuted, 136-u32 rows) -> smem ONCE: 8704 uint4 = 34 x 256
    {
        const uint4* src = (const uint4*)g_W1bf;
        uint4* dst = (uint4*)w1S;
#pragma unroll 4
        for (int it = 0; it < 34; it++) dst[it * 256 + tid] = src[it * 256 + tid];
    }
    betaS[tid] = beta[tid];

    const int END = BB * NCH;

    // prologue: stage first tile (own rows) + own-half hp copy
    {
        int tl0 = blockIdx.x;
        int b0 = tl0 >> 3, l00 = (tl0 & 7) << 7;
        const float* wrow = enc + ((size_t)b0 * LL + l00 + stage_m0) * DD;
        char* sdst = encS + stage_m0 * ROWB;
#pragma unroll 8
        for (int it = 0; it < 32; it++) {
            int idx = it * 32 + lane;
            int rl = idx >> 6;
            int c4 = idx & 63;
            float4 v = *(const float4*)(wrow + rl * DD + c4 * 4);
            __nv_bfloat162 p0 = __floats2bfloat162_rn(v.x, v.y);
            __nv_bfloat162 p1 = __floats2bfloat162_rn(v.z, v.w);
            int k0 = 4 * c4;
            *(uint32_t*)(sdst + rl * ROWB + kperm(k0) * 4)     = *(uint32_t*)&p0;
            *(uint32_t*)(sdst + rl * ROWB + kperm(k0 + 2) * 4) = *(uint32_t*)&p1;
        }
        hpMy[p] = g_hp[b0 * DD + p];
        hpMy[p + 128] = g_hp[b0 * DD + p + 128];
    }

    for (int tl = blockIdx.x; tl < END; tl += NSM) {
        int b = tl >> 3, ch = tl & 7, l0 = ch << 7;
        const float* encB = enc + ((size_t)b * LL + l0) * DD;

        named_bar(1 + half);   // own half staged (+ own hp copy)

        // ---- MMA mainloop: warp tile rows [mg*64,+64) x cols [ng*64,+64)
        float acc[4][8][4];
#pragma unroll
        for (int mi = 0; mi < 4; mi++)
#pragma unroll
            for (int jt = 0; jt < 8; jt++)
#pragma unroll
                for (int i = 0; i < 4; i++) acc[mi][jt][i] = 0.f;

        const char* abase = encS + (mg * 64 + g) * ROWB + t * 8;
        const char* bbase = w1S + (ng * 64 + g) * ROWB + t * 8;
#pragma unroll
        for (int kb = 0; kb < 16; kb++) {
            uint2 alo[4], ahi[4];
#pragma unroll
            for (int mi = 0; mi < 4; mi++) {
                const char* pa = abase + mi * 16 * ROWB + kb * 32;
                alo[mi] = *(const uint2*)(pa);
                ahi[mi] = *(const uint2*)(pa + 8 * ROWB);
            }
#pragma unroll
            for (int jt = 0; jt < 8; jt++) {
                uint2 bf = *(const uint2*)(bbase + jt * 8 * ROWB + kb * 32);
#pragma unroll
                for (int mi = 0; mi < 4; mi++)
                    mma_bf16(acc[mi][jt], alo[mi].x, ahi[mi].x, alo[mi].y, ahi[mi].y, bf.x, bf.y);
            }
        }

        // ---- epilogue: partial scores over this warp's 64-col range
#pragma unroll
        for (int mi = 0; mi < 4; mi++) {
            float s0 = 0.f, s1 = 0.f;
#pragma unroll
            for (int jt = 0; jt < 8; jt++) {
                int c = ng * 64 + jt * 8 + t * 2;
                float b0 = betaS[c], b1 = betaS[c + 1];
                float h0v = hpMy[c], h1v = hpMy[c + 1];
                s0 += b0 * tanh_fast(acc[mi][jt][0] + h0v) + b1 * tanh_fast(acc[mi][jt][1] + h1v);
                s1 += b0 * tanh_fast(acc[mi][jt][2] + h0v) + b1 * tanh_fast(acc[mi][jt][3] + h1v);
            }
            s0 += __shfl_xor_sync(0xffffffffu, s0, 1);
            s0 += __shfl_xor_sync(0xffffffffu, s0, 2);
            s1 += __shfl_xor_sync(0xffffffffu, s1, 1);
            s1 += __shfl_xor_sync(0xffffffffu, s1, 2);
            if (t == 0) {
                int row = mg * 64 + mi * 16 + g;
                sred[row * 5 + ng] = s0;
                sred[(row + 8) * 5 + ng] = s1;
            }
        }
        __syncthreads();   // S1: sred complete, encS/hpS free for restage

        if (tid < 128) {
            float s = sred[tid * 5] + sred[tid * 5 + 1] + sred[tid * 5 + 2] + sred[tid * 5 + 3];
            wS[tid] = expf(s);
        }
        __syncthreads();   // S2: wS complete

        if (tid < 32) {
            float ps = wS[tid] + wS[tid + 32] + wS[tid + 64] + wS[tid + 96];
#pragma unroll
            for (int o = 16; o > 0; o >>= 1) ps += __shfl_down_sync(0xffffffffu, ps, o);
            if (tid == 0) g_partS[b * NCH + ch] = ps;
        }

        // ---- FUSED TAIL: stage next tile (own rows) + context (own half rows)
        int tn = tl + NSM;
        if (tn < END) {
            int bn = tn >> 3, l0n = (tn & 7) << 7;
            const float* wrow = enc + ((size_t)bn * LL + l0n + stage_m0) * DD;
            char* sdst = encS + stage_m0 * ROWB;
#pragma unroll 8
            for (int it = 0; it < 32; it++) {
                int idx = it * 32 + lane;
                int rl = idx >> 6;
                int c4 = idx & 63;
                float4 v = *(const float4*)(wrow + rl * DD + c4 * 4);
                __nv_bfloat162 p0 = __floats2bfloat162_rn(v.x, v.y);
                __nv_bfloat162 p1 = __floats2bfloat162_rn(v.z, v.w);
                int k0 = 4 * c4;
                *(uint32_t*)(sdst + rl * ROWB + kperm(k0) * 4)     = *(uint32_t*)&p0;
                *(uint32_t*)(sdst + rl * ROWB + kperm(k0 + 2) * 4) = *(uint32_t*)&p1;
            }
            hpMy[p] = g_hp[bn * DD + p];
            hpMy[p + 128] = g_hp[bn * DD + p + 128];
        }

        // context: own half rows, fp32 from gmem (L2-hot), write half-partial
        {
            float C0 = 0.f, C1 = 0.f;
            const float* base = encB + (half * 64) * DD + 2 * p;
            const float* wHalf = wS + half * 64;
#pragma unroll 8
            for (int r = 0; r < 64; r++) {
                float2 v = *(const float2*)(base + r * DD);
                float w = wHalf[r];
                C0 += w * v.x;
                C1 += w * v.y;
            }
            float* dst = g_partC + ((size_t)(b * NCH + ch) * 2 + half) * DD;
            dst[2 * p] = C0;
            dst[2 * p + 1] = C1;
        }
        // loop top named_bar(1+half) waits for own half's staging
    }
}

// ---------------------------------------------------------------------------
// 6) context = sum(partC halves) / sum(partS)
// ---------------------------------------------------------------------------
__global__ void ctx_reduce_kernel() {
    int b = blockIdx.x, d = threadIdx.x;
    float S = 0.f, C = 0.f;
#pragma unroll
    for (int c = 0; c < NCH; c++) {
        S += g_partS[b * NCH + c];
        C += g_partC[((b * NCH + c) * 2) * DD + d] + g_partC[((b * NCH + c) * 2 + 1) * DD + d];
    }
    g_ctx[b * DD + d] = C / S;
}

// ---------------------------------------------------------------------------
// 7) o_new GEMM (unchanged)
// ---------------------------------------------------------------------------
__global__ __launch_bounds__(256) void onew_gemm_kernel(
    const float* __restrict__ W3, float* __restrict__ out) {
    __shared__ float aT[32 * 65];
    __shared__ float bS[32 * 65];
    int n0 = blockIdx.x * 64;
    int m0 = blockIdx.y * 64;
    int tid = threadIdx.x;
    int tx = tid & 15, ty = tid >> 4;

    float acc[4][4];
#pragma unroll
    for (int i = 0; i < 4; i++)
#pragma unroll
        for (int j = 0; j < 4; j++) acc[i][j] = 0.f;

    for (int k0 = 0; k0 < 512; k0 += 32) {
        __syncthreads();
#pragma unroll
        for (int rep = 0; rep < 8; rep++) {
            int idx = rep * 256 + tid;
            int r = idx >> 5, kk = idx & 31;
            int kg = k0 + kk;
            aT[kk * 65 + r] = (kg < 256) ? out[(m0 + r) * HH + kg]
                                         : g_ctx[(m0 + r) * DD + (kg - 256)];
        }
#pragma unroll
        for (int rep = 0; rep < 8; rep++) {
            int idx = rep * 256 + tid;
            int j = idx >> 5, kk = idx & 31;
            bS[kk * 65 + j] = W3[(n0 + j) * 512 + k0 + kk];
        }
        __syncthreads();
#pragma unroll
        for (int kk = 0; kk < 32; kk++) {
            float a[4], w[4];
#pragma unroll
            for (int i = 0; i < 4; i++) a[i] = aT[kk * 65 + ty * 4 + i];
#pragma unroll
            for (int j = 0; j < 4; j++) w[j] = bS[kk * 65 + tx * 4 + j];
#pragma unroll
            for (int i = 0; i < 4; i++)
#pragma unroll
                for (int j = 0; j < 4; j++) acc[i][j] += a[i] * w[j];
        }
    }
#pragma unroll
    for (int i = 0; i < 4; i++)
#pragma unroll
        for (int j = 0; j < 4; j++)
            out[2 * BB * HH + (m0 + ty * 4 + i) * HH + n0 + tx * 4 + j] = tanhf(acc[i][j]);
}

// ---------------------------------------------------------------------------
// 8) logits GEMM (unchanged)
// ---------------------------------------------------------------------------
__global__ __launch_bounds__(256) void logit_gemm_kernel(
    const float* __restrict__ Wout, const float* __restrict__ out) {
    __shared__ float aT[32 * 65];
    __shared__ float bS[32 * 65];
    int n0 = blockIdx.x * 64;
    int m0 = blockIdx.y * 64;
    int tid = threadIdx.x;
    int tx = tid & 15, ty = tid >> 4;
    const float* onew = out + 2 * BB * HH;

    float acc[4][4];
#pragma unroll
    for (int i = 0; i < 4; i++)
#pragma unroll
        for (int j = 0; j < 4; j++) acc[i][j] = 0.f;

    for (int k0 = 0; k0 < HH; k0 += 32) {
        __syncthreads();
#pragma unroll
        for (int rep = 0; rep < 8; rep++) {
            int idx = rep * 256 + tid;
            int r = idx >> 5, kk = idx & 31;
            aT[kk * 65 + r] = onew[(m0 + r) * HH + k0 + kk];
        }
#pragma unroll
        for (int rep = 0; rep < 8; rep++) {
            int idx = rep * 256 + tid;
            int j = idx >> 5, kk = idx & 31;
            int jg = n0 + j;
            bS[kk * 65 + j] = (jg < NOUT) ? Wout[jg * HH + k0 + kk] : 0.f;
        }
        __syncthreads();
#pragma unroll
        for (int kk = 0; kk < 32; kk++) {
            float a[4], w[4];
#pragma unroll
            for (int i = 0; i < 4; i++) a[i] = aT[kk * 65 + ty * 4 + i];
#pragma unroll
            for (int j = 0; j < 4; j++) w[j] = bS[kk * 65 + tx * 4 + j];
#pragma unroll
            for (int i = 0; i < 4; i++)
#pragma unroll
                for (int j = 0; j < 4; j++) acc[i][j] += a[i] * w[j];
        }
    }
#pragma unroll
    for (int i = 0; i < 4; i++) {
        int row = m0 + ty * 4 + i;
#pragma unroll
        for (int j = 0; j < 4; j++) {
            int col = n0 + tx * 4 + j;
            if (col < NOUT) g_logits[row * NOUT + col] = acc[i][j];
        }
    }
}

// ---------------------------------------------------------------------------
// 9) logit softmax
// ---------------------------------------------------------------------------
__global__ void softmax_logit_kernel(float* __restrict__ out) {
    __shared__ float lg[NOUT];
    __shared__ float red;
    int b = blockIdx.x, t = threadIdx.x;
    if (t < NOUT) lg[t] = g_logits[b * NOUT + t];
    __syncthreads();
    if (t == 0) {
        float m = lg[0];
        for (int i = 1; i < NOUT; i++) m = fmaxf(m, lg[i]);
        red = m;
    }
    __syncthreads();
    float e = (t < NOUT) ? expf(lg[t] - red) : 0.f;
    __syncthreads();
    if (t < NOUT) lg[t] = e;
    __syncthreads();
    if (t == 0) {
        float s = 0.f;
        for (int i = 0; i < NOUT; i++) s += lg[i];
        red = s;
    }
    __syncthreads();
    if (t < NOUT) out[3 * BB * HH + b * NOUT + t] = lg[t] / red;
}

// ---------------------------------------------------------------------------
extern "C" void kernel_launch(void* const* d_in, const int* in_sizes, int n_in,
                              void* d_out, int out_size) {
    const float* h0      = (const float*)d_in[0];
    const float* c0      = (const float*)d_in[1];
    const float* o_t     = (const float*)d_in[2];
    const float* enc_out = (const float*)d_in[3];
    const int*   lt      = (const int*)  d_in[4];
    const float* emb     = (const float*)d_in[5];
    const float* W_ih    = (const float*)d_in[6];
    const float* W_hh    = (const float*)d_in[7];
    const float* b_ih    = (const float*)d_in[8];
    const float* b_hh    = (const float*)d_in[9];
    const float* W1      = (const float*)d_in[10];
    const float* W2      = (const float*)d_in[11];
    const float* W3      = (const float*)d_in[12];
    const float* W_out   = (const float*)d_in[13];
    const float* beta    = (const float*)d_in[14];
    float* out = (float*)d_out;

    cudaFuncSetAttribute(attn_mma_kernel, cudaFuncAttributeMaxDynamicSharedMemorySize, SM_TOTAL);

    prep_A_kernel<<<BB, KIN>>>(emb, lt, o_t, h0);
    prep_W1_kernel<<<256, 128>>>(W1);
    gates_gemm_kernel<<<dim3(16, 4), 256>>>(W_ih, W_hh, b_ih, b_hh);
    cell_kernel<<<BB, HH>>>(c0, out);
    hproj_gemm_kernel<<<dim3(4, 4), 256>>>(W2, out);
    attn_mma_kernel<<<NSM, 256, SM_TOTAL>>>(enc_out, beta);
    ctx_reduce_kernel<<<BB, DD>>>();
    onew_gemm_kernel<<<dim3(4, 4), 256>>>(W3, out);
    logit_gemm_kernel<<<dim3(3, 4), 256>>>(W_out, out);
    softmax_logit_kernel<<<BB, 192>>>(out);
}

// round 13
// speedup vs baseline: 1.0757x; 1.0057x over previous
#include <cuda_runtime.h>
#include <cuda_bf16.h>
#include <math.h>
#include <cstdint>

#define BB   256
#define LL   1024
#define DD   256
#define HH   256
#define EMBD 128
#define NOUT 172
#define KIN  640
#define NCH  8     // L / 128
#define NSM  148

// ---------------- scratch (device globals; no allocation allowed) ----------
__device__ float g_A[BB * KIN];
__device__ float g_gates[BB * 4 * HH];
__device__ float g_hp[BB * DD];
__device__ float g_ctx[BB * DD];
__device__ float g_partS[BB * NCH];
__device__ float g_partC[BB * NCH * 2 * DD];   // two half-partials per tile
__device__ float g_logits[BB * NOUT];
__device__ uint32_t g_W1bf[256 * 136];   // W1 bf16, K-PERMUTED rows of 136 u32 (544 B)

// ---------------- helpers ---------------------------------------------------
__device__ __forceinline__ float tanh_fast(float x) {
    float y;
    asm("tanh.approx.f32 %0, %1;" : "=f"(y) : "f"(x));
    return y;
}
__device__ __forceinline__ float sigmoidf(float x) {
    return 1.0f / (1.0f + expf(-x));
}
__device__ __forceinline__ void mma_bf16(float* c,
                                         uint32_t a0, uint32_t a1, uint32_t a2, uint32_t a3,
                                         uint32_t b0, uint32_t b1) {
    asm volatile(
        "mma.sync.aligned.m16n8k16.row.col.f32.bf16.bf16.f32 "
        "{%0,%1,%2,%3}, {%4,%5,%6,%7}, {%8,%9}, {%0,%1,%2,%3};"
        : "+f"(c[0]), "+f"(c[1]), "+f"(c[2]), "+f"(c[3])
        : "r"(a0), "r"(a1), "r"(a2), "r"(a3), "r"(b0), "r"(b1));
}
__device__ __forceinline__ void named_bar(int id, int cnt) {
    asm volatile("bar.sync %0, %1;" :: "r"(id), "r"(cnt) : "memory");
}

// attn smem layout (bytes) — ROWB 544 = 136 u32 (8-bank row shift, conflict-free)
#define ROWB    544
#define SM_W1     0                   // 256 x 544 = 139264
#define SM_ENC    139264              // 128 x 544 = 69632
#define SM_HP     208896              // 2 x 256 f32 (per-half copies) = 2048
#define SM_BETA   210944              // 256 f32
#define SM_WS     211968              // 128 f32
#define SM_SRED   212480              // 128 x 5 f32 = 2560
#define SM_TOTAL  215040

// K-pair permutation: even k -> pos = (k>>4)*8 + ((k&7)>>1)*2 + ((k>>3)&1)
__device__ __forceinline__ int kperm(int k) {
    return ((k >> 4) << 3) + (((k & 7) >> 1) << 1) + ((k >> 3) & 1);
}

// ---------------------------------------------------------------------------
// 1) Build LSTM input rows
// ---------------------------------------------------------------------------
__global__ void prep_A_kernel(const float* __restrict__ emb,
                              const int* __restrict__ lt,
                              const float* __restrict__ o_t,
                              const float* __restrict__ h0) {
    int b = blockIdx.x;
    int k = threadIdx.x;
    float v;
    if (k < EMBD)       v = emb[lt[b] * EMBD + k];
    else if (k < 384)   v = o_t[b * HH + (k - EMBD)];
    else                v = h0[b * HH + (k - 384)];
    g_A[b * KIN + k] = v;
}

// ---------------------------------------------------------------------------
// 1b) Pre-pack W1 -> bf16, 136-u32 rows, K-permuted
// ---------------------------------------------------------------------------
__global__ void prep_W1_kernel(const float* __restrict__ W1) {
    int n = blockIdx.x;
    int kp = threadIdx.x;
    int k = 2 * kp;
    __nv_bfloat162 h = __floats2bfloat162_rn(W1[n * DD + k], W1[n * DD + k + 1]);
    g_W1bf[n * 136 + kperm(k)] = *(uint32_t*)&h;
    if (kp < 8) g_W1bf[n * 136 + 128 + kp] = 0u;
}

// ---------------------------------------------------------------------------
// 2) gates GEMM (unchanged)
// ---------------------------------------------------------------------------
__global__ __launch_bounds__(256) void gates_gemm_kernel(
    const float* __restrict__ W_ih, const float* __restrict__ W_hh,
    const float* __restrict__ b_ih, const float* __restrict__ b_hh) {
    __shared__ float aT[32 * 65];
    __shared__ float bS[32 * 65];
    int n0 = blockIdx.x * 64;
    int m0 = blockIdx.y * 64;
    int tid = threadIdx.x;
    int tx = tid & 15, ty = tid >> 4;

    float acc[4][4];
#pragma unroll
    for (int i = 0; i < 4; i++)
#pragma unroll
        for (int j = 0; j < 4; j++) acc[i][j] = 0.f;

    for (int k0 = 0; k0 < KIN; k0 += 32) {
        __syncthreads();
#pragma unroll
        for (int rep = 0; rep < 8; rep++) {
            int idx = rep * 256 + tid;
            int r = idx >> 5, kk = idx & 31;
            aT[kk * 65 + r] = g_A[(m0 + r) * KIN + k0 + kk];
        }
#pragma unroll
        for (int rep = 0; rep < 8; rep++) {
            int idx = rep * 256 + tid;
            int j = idx >> 5, kk = idx & 31;
            int kg = k0 + kk;
            int jg = n0 + j;
            bS[kk * 65 + j] = (kg < 384) ? W_ih[jg * 384 + kg] : W_hh[jg * 256 + (kg - 384)];
        }
        __syncthreads();
#pragma unroll
        for (int kk = 0; kk < 32; kk++) {
            float a[4], w[4];
#pragma unroll
            for (int i = 0; i < 4; i++) a[i] = aT[kk * 65 + ty * 4 + i];
#pragma unroll
            for (int j = 0; j < 4; j++) w[j] = bS[kk * 65 + tx * 4 + j];
#pragma unroll
            for (int i = 0; i < 4; i++)
#pragma unroll
                for (int j = 0; j < 4; j++) acc[i][j] += a[i] * w[j];
        }
    }
#pragma unroll
    for (int i = 0; i < 4; i++) {
        int row = m0 + ty * 4 + i;
#pragma unroll
        for (int j = 0; j < 4; j++) {
            int col = n0 + tx * 4 + j;
            g_gates[row * 1024 + col] = acc[i][j] + b_ih[col] + b_hh[col];
        }
    }
}

// ---------------------------------------------------------------------------
// 3) LSTM cell
// ---------------------------------------------------------------------------
__global__ void cell_kernel(const float* __restrict__ c0, float* __restrict__ out) {
    int b = blockIdx.x, d = threadIdx.x;
    const float* g = g_gates + b * 1024;
    float ig = g[d], fg = g[256 + d], gg = g[512 + d], og = g[768 + d];
    float c = sigmoidf(fg) * c0[b * HH + d] + sigmoidf(ig) * tanhf(gg);
    float h = sigmoidf(og) * tanhf(c);
    out[b * HH + d] = h;
    out[BB * HH + b * HH + d] = c;
}

// ---------------------------------------------------------------------------
// 4) hp GEMM (unchanged)
// ---------------------------------------------------------------------------
__global__ __launch_bounds__(256) void hproj_gemm_kernel(
    const float* __restrict__ W2, const float* __restrict__ out) {
    __shared__ float aT[32 * 65];
    __shared__ float bS[32 * 65];
    int n0 = blockIdx.x * 64;
    int m0 = blockIdx.y * 64;
    int tid = threadIdx.x;
    int tx = tid & 15, ty = tid >> 4;

    float acc[4][4];
#pragma unroll
    for (int i = 0; i < 4; i++)
#pragma unroll
        for (int j = 0; j < 4; j++) acc[i][j] = 0.f;

    for (int k0 = 0; k0 < HH; k0 += 32) {
        __syncthreads();
#pragma unroll
        for (int rep = 0; rep < 8; rep++) {
            int idx = rep * 256 + tid;
            int r = idx >> 5, kk = idx & 31;
            aT[kk * 65 + r] = out[(m0 + r) * HH + k0 + kk];
        }
#pragma unroll
        for (int rep = 0; rep < 8; rep++) {
            int idx = rep * 256 + tid;
            int j = idx >> 5, kk = idx & 31;
            bS[kk * 65 + j] = W2[(n0 + j) * HH + k0 + kk];
        }
        __syncthreads();
#pragma unroll
        for (int kk = 0; kk < 32; kk++) {
            float a[4], w[4];
#pragma unroll
            for (int i = 0; i < 4; i++) a[i] = aT[kk * 65 + ty * 4 + i];
#pragma unroll
            for (int j = 0; j < 4; j++) w[j] = bS[kk * 65 + tx * 4 + j];
#pragma unroll
            for (int i = 0; i < 4; i++)
#pragma unroll
                for (int j = 0; j < 4; j++) acc[i][j] += a[i] * w[j];
        }
    }
#pragma unroll
    for (int i = 0; i < 4; i++)
#pragma unroll
        for (int j = 0; j < 4; j++)
            g_hp[(m0 + ty * 4 + i) * DD + n0 + tx * 4 + j] = acc[i][j];
}

// ---------------------------------------------------------------------------
// 5) PERSISTENT attention, 512 threads (16 warps = 4m x 4n, warp tile 32x64).
//    Higher SMSP occupancy to hide LDS/MUFU/context behind the HMMA pipe.
// ---------------------------------------------------------------------------
__global__ __launch_bounds__(512, 1) void attn_mma_kernel(
    const float* __restrict__ enc, const float* __restrict__ beta) {
    extern __shared__ char sm[];
    float* hpS   = (float*)(sm + SM_HP);     // [2][256]
    float* betaS = (float*)(sm + SM_BETA);
    float* wS    = (float*)(sm + SM_WS);
    float* sred  = (float*)(sm + SM_SRED);
    char*  encS  = sm + SM_ENC;
    char*  w1S   = sm + SM_W1;

    int tid = threadIdx.x, wid = tid >> 5, lane = tid & 31;
    int g = lane >> 2, t = lane & 3;
    int mg = wid >> 2, ng = wid & 3;       // 4 m-groups x 4 n-groups
    int half = mg >> 1;                    // warps 0-7: half 0; 8-15: half 1
    int p2 = tid & 255;                    // id within half (0..255)
    int stage_m0 = wid * 8;                // 8 staging rows per warp
    float* hpMy = hpS + half * 256;

    // W1 bf16 (K-permuted, 136-u32 rows) -> smem ONCE: 8704 uint4 = 17 x 512
    {
        const uint4* src = (const uint4*)g_W1bf;
        uint4* dst = (uint4*)w1S;
#pragma unroll 4
        for (int it = 0; it < 17; it++) dst[it * 512 + tid] = src[it * 512 + tid];
    }
    if (tid < 256) betaS[tid] = beta[tid];

    const int END = BB * NCH;

    // prologue: stage first tile (own 8 rows) + own-half hp copy
    {
        int tl0 = blockIdx.x;
        int b0 = tl0 >> 3, l00 = (tl0 & 7) << 7;
        const float* wrow = enc + ((size_t)b0 * LL + l00 + stage_m0) * DD;
        char* sdst = encS + stage_m0 * ROWB;
#pragma unroll 8
        for (int it = 0; it < 16; it++) {
            int idx = it * 32 + lane;        // 512 float4 per warp (8 rows x 64)
            int rl = idx >> 6;
            int c4 = idx & 63;
            float4 v = *(const float4*)(wrow + rl * DD + c4 * 4);
            __nv_bfloat162 p0 = __floats2bfloat162_rn(v.x, v.y);
            __nv_bfloat162 p1 = __floats2bfloat162_rn(v.z, v.w);
            int k0 = 4 * c4;
            *(uint32_t*)(sdst + rl * ROWB + kperm(k0) * 4)     = *(uint32_t*)&p0;
            *(uint32_t*)(sdst + rl * ROWB + kperm(k0 + 2) * 4) = *(uint32_t*)&p1;
        }
        hpMy[p2] = g_hp[b0 * DD + p2];
    }

    for (int tl = blockIdx.x; tl < END; tl += NSM) {
        int b = tl >> 3, ch = tl & 7, l0 = ch << 7;
        const float* encB = enc + ((size_t)b * LL + l0) * DD;

        named_bar(1 + half, 256);   // own half staged (+ own hp copy)

        // ---- MMA mainloop: warp tile rows [mg*32,+32) x cols [ng*64,+64)
        float acc[2][8][4];
#pragma unroll
        for (int mi = 0; mi < 2; mi++)
#pragma unroll
            for (int jt = 0; jt < 8; jt++)
#pragma unroll
                for (int i = 0; i < 4; i++) acc[mi][jt][i] = 0.f;

        const char* abase = encS + (mg * 32 + g) * ROWB + t * 8;
        const char* bbase = w1S + (ng * 64 + g) * ROWB + t * 8;
#pragma unroll
        for (int kb = 0; kb < 16; kb++) {
            uint2 alo[2], ahi[2];
#pragma unroll
            for (int mi = 0; mi < 2; mi++) {
                const char* pa = abase + mi * 16 * ROWB + kb * 32;
                alo[mi] = *(const uint2*)(pa);
                ahi[mi] = *(const uint2*)(pa + 8 * ROWB);
            }
#pragma unroll
            for (int jt = 0; jt < 8; jt++) {
                uint2 bf = *(const uint2*)(bbase + jt * 8 * ROWB + kb * 32);
#pragma unroll
                for (int mi = 0; mi < 2; mi++)
                    mma_bf16(acc[mi][jt], alo[mi].x, ahi[mi].x, alo[mi].y, ahi[mi].y, bf.x, bf.y);
            }
        }

        // ---- epilogue: partial scores over this warp's 64-col range
#pragma unroll
        for (int mi = 0; mi < 2; mi++) {
            float s0 = 0.f, s1 = 0.f;
#pragma unroll
            for (int jt = 0; jt < 8; jt++) {
                int c = ng * 64 + jt * 8 + t * 2;
                float b0 = betaS[c], b1 = betaS[c + 1];
                float h0v = hpMy[c], h1v = hpMy[c + 1];
                s0 += b0 * tanh_fast(acc[mi][jt][0] + h0v) + b1 * tanh_fast(acc[mi][jt][1] + h1v);
                s1 += b0 * tanh_fast(acc[mi][jt][2] + h0v) + b1 * tanh_fast(acc[mi][jt][3] + h1v);
            }
            s0 += __shfl_xor_sync(0xffffffffu, s0, 1);
            s0 += __shfl_xor_sync(0xffffffffu, s0, 2);
            s1 += __shfl_xor_sync(0xffffffffu, s1, 1);
            s1 += __shfl_xor_sync(0xffffffffu, s1, 2);
            if (t == 0) {
                int row = mg * 32 + mi * 16 + g;
                sred[row * 5 + ng] = s0;
                sred[(row + 8) * 5 + ng] = s1;
            }
        }
        __syncthreads();   // S1: sred complete, encS/hpS free for restage

        if (tid < 128) {
            float s = sred[tid * 5] + sred[tid * 5 + 1] + sred[tid * 5 + 2] + sred[tid * 5 + 3];
            wS[tid] = expf(s);
        }
        __syncthreads();   // S2: wS complete

        if (tid < 32) {
            float ps = wS[tid] + wS[tid + 32] + wS[tid + 64] + wS[tid + 96];
#pragma unroll
            for (int o = 16; o > 0; o >>= 1) ps += __shfl_down_sync(0xffffffffu, ps, o);
            if (tid == 0) g_partS[b * NCH + ch] = ps;
        }

        // ---- FUSED TAIL: stage next tile (own rows) + context (own half)
        int tn = tl + NSM;
        if (tn < END) {
            int bn = tn >> 3, l0n = (tn & 7) << 7;
            const float* wrow = enc + ((size_t)bn * LL + l0n + stage_m0) * DD;
            char* sdst = encS + stage_m0 * ROWB;
#pragma unroll 8
            for (int it = 0; it < 16; it++) {
                int idx = it * 32 + lane;
                int rl = idx >> 6;
                int c4 = idx & 63;
                float4 v = *(const float4*)(wrow + rl * DD + c4 * 4);
                __nv_bfloat162 p0 = __floats2bfloat162_rn(v.x, v.y);
                __nv_bfloat162 p1 = __floats2bfloat162_rn(v.z, v.w);
                int k0 = 4 * c4;
                *(uint32_t*)(sdst + rl * ROWB + kperm(k0) * 4)     = *(uint32_t*)&p0;
                *(uint32_t*)(sdst + rl * ROWB + kperm(k0 + 2) * 4) = *(uint32_t*)&p1;
            }
            hpMy[p2] = g_hp[bn * DD + p2];
        }

        // context: own half rows (64), one column per thread, fp32 from gmem
        {
            float C = 0.f;
            const float* base = encB + (half * 64) * DD + p2;
            const float* wHalf = wS + half * 64;
#pragma unroll 8
            for (int r = 0; r < 64; r++) C += wHalf[r] * base[r * DD];
            g_partC[((size_t)(b * NCH + ch) * 2 + half) * DD + p2] = C;
        }
        // loop-top named_bar waits for own half's staging
    }
}

// ---------------------------------------------------------------------------
// 6) context = sum(partC halves) / sum(partS)
// ---------------------------------------------------------------------------
__global__ void ctx_reduce_kernel() {
    int b = blockIdx.x, d = threadIdx.x;
    float S = 0.f, C = 0.f;
#pragma unroll
    for (int c = 0; c < NCH; c++) {
        S += g_partS[b * NCH + c];
        C += g_partC[((b * NCH + c) * 2) * DD + d] + g_partC[((b * NCH + c) * 2 + 1) * DD + d];
    }
    g_ctx[b * DD + d] = C / S;
}

// ---------------------------------------------------------------------------
// 7) o_new GEMM (unchanged)
// ---------------------------------------------------------------------------
__global__ __launch_bounds__(256) void onew_gemm_kernel(
    const float* __restrict__ W3, float* __restrict__ out) {
    __shared__ float aT[32 * 65];
    __shared__ float bS[32 * 65];
    int n0 = blockIdx.x * 64;
    int m0 = blockIdx.y * 64;
    int tid = threadIdx.x;
    int tx = tid & 15, ty = tid >> 4;

    float acc[4][4];
#pragma unroll
    for (int i = 0; i < 4; i++)
#pragma unroll
        for (int j = 0; j < 4; j++) acc[i][j] = 0.f;

    for (int k0 = 0; k0 < 512; k0 += 32) {
        __syncthreads();
#pragma unroll
        for (int rep = 0; rep < 8; rep++) {
            int idx = rep * 256 + tid;
            int r = idx >> 5, kk = idx & 31;
            int kg = k0 + kk;
            aT[kk * 65 + r] = (kg < 256) ? out[(m0 + r) * HH + kg]
                                         : g_ctx[(m0 + r) * DD + (kg - 256)];
        }
#pragma unroll
        for (int rep = 0; rep < 8; rep++) {
            int idx = rep * 256 + tid;
            int j = idx >> 5, kk = idx & 31;
            bS[kk * 65 + j] = W3[(n0 + j) * 512 + k0 + kk];
        }
        __syncthreads();
#pragma unroll
        for (int kk = 0; kk < 32; kk++) {
            float a[4], w[4];
#pragma unroll
            for (int i = 0; i < 4; i++) a[i] = aT[kk * 65 + ty * 4 + i];
#pragma unroll
            for (int j = 0; j < 4; j++) w[j] = bS[kk * 65 + tx * 4 + j];
#pragma unroll
            for (int i = 0; i < 4; i++)
#pragma unroll
                for (int j = 0; j < 4; j++) acc[i][j] += a[i] * w[j];
        }
    }
#pragma unroll
    for (int i = 0; i < 4; i++)
#pragma unroll
        for (int j = 0; j < 4; j++)
            out[2 * BB * HH + (m0 + ty * 4 + i) * HH + n0 + tx * 4 + j] = tanhf(acc[i][j]);
}

// ---------------------------------------------------------------------------
// 8) logits GEMM (unchanged)
// ---------------------------------------------------------------------------
__global__ __launch_bounds__(256) void logit_gemm_kernel(
    const float* __restrict__ Wout, const float* __restrict__ out) {
    __shared__ float aT[32 * 65];
    __shared__ float bS[32 * 65];
    int n0 = blockIdx.x * 64;
    int m0 = blockIdx.y * 64;
    int tid = threadIdx.x;
    int tx = tid & 15, ty = tid >> 4;
    const float* onew = out + 2 * BB * HH;

    float acc[4][4];
#pragma unroll
    for (int i = 0; i < 4; i++)
#pragma unroll
        for (int j = 0; j < 4; j++) acc[i][j] = 0.f;

    for (int k0 = 0; k0 < HH; k0 += 32) {
        __syncthreads();
#pragma unroll
        for (int rep = 0; rep < 8; rep++) {
            int idx = rep * 256 + tid;
            int r = idx >> 5, kk = idx & 31;
            aT[kk * 65 + r] = onew[(m0 + r) * HH + k0 + kk];
        }
#pragma unroll
        for (int rep = 0; rep < 8; rep++) {
            int idx = rep * 256 + tid;
            int j = idx >> 5, kk = idx & 31;
            int jg = n0 + j;
            bS[kk * 65 + j] = (jg < NOUT) ? Wout[jg * HH + k0 + kk] : 0.f;
        }
        __syncthreads();
#pragma unroll
        for (int kk = 0; kk < 32; kk++) {
            float a[4], w[4];
#pragma unroll
            for (int i = 0; i < 4; i++) a[i] = aT[kk * 65 + ty * 4 + i];
#pragma unroll
            for (int j = 0; j < 4; j++) w[j] = bS[kk * 65 + tx * 4 + j];
#pragma unroll
            for (int i = 0; i < 4; i++)
#pragma unroll
                for (int j = 0; j < 4; j++) acc[i][j] += a[i] * w[j];
        }
    }
#pragma unroll
    for (int i = 0; i < 4; i++) {
        int row = m0 + ty * 4 + i;
#pragma unroll
        for (int j = 0; j < 4; j++) {
            int col = n0 + tx * 4 + j;
            if (col < NOUT) g_logits[row * NOUT + col] = acc[i][j];
        }
    }
}

// ---------------------------------------------------------------------------
// 9) logit softmax
// ---------------------------------------------------------------------------
__global__ void softmax_logit_kernel(float* __restrict__ out) {
    __shared__ float lg[NOUT];
    __shared__ float red;
    int b = blockIdx.x, t = threadIdx.x;
    if (t < NOUT) lg[t] = g_logits[b * NOUT + t];
    __syncthreads();
    if (t == 0) {
        float m = lg[0];
        for (int i = 1; i < NOUT; i++) m = fmaxf(m, lg[i]);
        red = m;
    }
    __syncthreads();
    float e = (t < NOUT) ? expf(lg[t] - red) : 0.f;
    __syncthreads();
    if (t < NOUT) lg[t] = e;
    __syncthreads();
    if (t == 0) {
        float s = 0.f;
        for (int i = 0; i < NOUT; i++) s += lg[i];
        red = s;
    }
    __syncthreads();
    if (t < NOUT) out[3 * BB * HH + b * NOUT + t] = lg[t] / red;
}

// ---------------------------------------------------------------------------
extern "C" void kernel_launch(void* const* d_in, const int* in_sizes, int n_in,
                              void* d_out, int out_size) {
    const float* h0      = (const float*)d_in[0];
    const float* c0      = (const float*)d_in[1];
    const float* o_t     = (const float*)d_in[2];
    const float* enc_out = (const float*)d_in[3];
    const int*   lt      = (const int*)  d_in[4];
    const float* emb     = (const float*)d_in[5];
    const float* W_ih    = (const float*)d_in[6];
    const float* W_hh    = (const float*)d_in[7];
    const float* b_ih    = (const float*)d_in[8];
    const float* b_hh    = (const float*)d_in[9];
    const float* W1      = (const float*)d_in[10];
    const float* W2      = (const float*)d_in[11];
    const float* W3      = (const float*)d_in[12];
    const float* W_out   = (const float*)d_in[13];
    const float* beta    = (const float*)d_in[14];
    float* out = (float*)d_out;

    cudaFuncSetAttribute(attn_mma_kernel, cudaFuncAttributeMaxDynamicSharedMemorySize, SM_TOTAL);

    prep_A_kernel<<<BB, KIN>>>(emb, lt, o_t, h0);
    prep_W1_kernel<<<256, 128>>>(W1);
    gates_gemm_kernel<<<dim3(16, 4), 256>>>(W_ih, W_hh, b_ih, b_hh);
    cell_kernel<<<BB, HH>>>(c0, out);
    hproj_gemm_kernel<<<dim3(4, 4), 256>>>(W2, out);
    attn_mma_kernel<<<NSM, 512, SM_TOTAL>>>(enc_out, beta);
    ctx_reduce_kernel<<<BB, DD>>>();
    onew_gemm_kernel<<<dim3(4, 4), 256>>>(W3, out);
    logit_gemm_kernel<<<dim3(3, 4), 256>>>(W_out, out);
    softmax_logit_kernel<<<BB, 192>>>(out);
}

// round 14
// speedup vs baseline: 1.0921x; 1.0153x over previous
#include <cuda_runtime.h>
#include <cuda_fp16.h>
#include <math.h>
#include <cstdint>

#define BB   256
#define LL   1024
#define DD   256
#define HH   256
#define EMBD 128
#define NOUT 172
#define KIN  640
#define NCH  8     // L / 128
#define NSM  148

// ---------------- scratch (device globals; no allocation allowed) ----------
__device__ float g_A[BB * KIN];
__device__ float g_gates[BB * 4 * HH];
__device__ float g_hp[BB * DD];
__device__ float g_ctx[BB * DD];
__device__ float g_partS[BB * NCH];
__device__ float g_partC[BB * NCH * 2 * DD];   // two half-partials per tile
__device__ float g_logits[BB * NOUT];
__device__ uint32_t g_W1h[256 * 136];   // W1 fp16, K-PERMUTED rows of 136 u32 (544 B)

// ---------------- helpers ---------------------------------------------------
__device__ __forceinline__ float tanh_fast(float x) {
    float y;
    asm("tanh.approx.f32 %0, %1;" : "=f"(y) : "f"(x));
    return y;
}
__device__ __forceinline__ float sigmoidf(float x) {
    return 1.0f / (1.0f + expf(-x));
}
// fp16-in, fp16-accum HMMA (m16n8k16). c = 2 packed half2 regs.
__device__ __forceinline__ void mma_f16(uint32_t* c,
                                        uint32_t a0, uint32_t a1, uint32_t a2, uint32_t a3,
                                        uint32_t b0, uint32_t b1) {
    asm volatile(
        "mma.sync.aligned.m16n8k16.row.col.f16.f16.f16.f16 "
        "{%0,%1}, {%2,%3,%4,%5}, {%6,%7}, {%0,%1};"
        : "+r"(c[0]), "+r"(c[1])
        : "r"(a0), "r"(a1), "r"(a2), "r"(a3), "r"(b0), "r"(b1));
}
__device__ __forceinline__ void named_bar(int id, int cnt) {
    asm volatile("bar.sync %0, %1;" :: "r"(id), "r"(cnt) : "memory");
}

// attn smem layout (bytes) — ROWB 544 = 136 u32 (8-bank row shift, conflict-free)
#define ROWB    544
#define SM_W1     0                   // 256 x 544 = 139264
#define SM_ENC    139264              // 128 x 544 = 69632
#define SM_HP     208896              // 2 x 256 f32 = 2048
#define SM_BETA   210944              // 256 f32
#define SM_WS     211968              // 128 f32
#define SM_SRED   212480              // 128 x 5 f32 = 2560
#define SM_TOTAL  215040

// K-pair permutation: even k -> pos = (k>>4)*8 + ((k&7)>>1)*2 + ((k>>3)&1)
__device__ __forceinline__ int kperm(int k) {
    return ((k >> 4) << 3) + (((k & 7) >> 1) << 1) + ((k >> 3) & 1);
}

// ---------------------------------------------------------------------------
// 1) Build LSTM input rows
// ---------------------------------------------------------------------------
__global__ void prep_A_kernel(const float* __restrict__ emb,
                              const int* __restrict__ lt,
                              const float* __restrict__ o_t,
                              const float* __restrict__ h0) {
    int b = blockIdx.x;
    int k = threadIdx.x;
    float v;
    if (k < EMBD)       v = emb[lt[b] * EMBD + k];
    else if (k < 384)   v = o_t[b * HH + (k - EMBD)];
    else                v = h0[b * HH + (k - 384)];
    g_A[b * KIN + k] = v;
}

// ---------------------------------------------------------------------------
// 1b) Pre-pack W1 -> fp16, 136-u32 rows, K-permuted
// ---------------------------------------------------------------------------
__global__ void prep_W1_kernel(const float* __restrict__ W1) {
    int n = blockIdx.x;
    int kp = threadIdx.x;
    int k = 2 * kp;
    __half2 h = __floats2half2_rn(W1[n * DD + k], W1[n * DD + k + 1]);
    g_W1h[n * 136 + kperm(k)] = *(uint32_t*)&h;
    if (kp < 8) g_W1h[n * 136 + 128 + kp] = 0u;
}

// ---------------------------------------------------------------------------
// 2) gates GEMM (unchanged)
// ---------------------------------------------------------------------------
__global__ __launch_bounds__(256) void gates_gemm_kernel(
    const float* __restrict__ W_ih, const float* __restrict__ W_hh,
    const float* __restrict__ b_ih, const float* __restrict__ b_hh) {
    __shared__ float aT[32 * 65];
    __shared__ float bS[32 * 65];
    int n0 = blockIdx.x * 64;
    int m0 = blockIdx.y * 64;
    int tid = threadIdx.x;
    int tx = tid & 15, ty = tid >> 4;

    float acc[4][4];
#pragma unroll
    for (int i = 0; i < 4; i++)
#pragma unroll
        for (int j = 0; j < 4; j++) acc[i][j] = 0.f;

    for (int k0 = 0; k0 < KIN; k0 += 32) {
        __syncthreads();
#pragma unroll
        for (int rep = 0; rep < 8; rep++) {
            int idx = rep * 256 + tid;
            int r = idx >> 5, kk = idx & 31;
            aT[kk * 65 + r] = g_A[(m0 + r) * KIN + k0 + kk];
        }
#pragma unroll
        for (int rep = 0; rep < 8; rep++) {
            int idx = rep * 256 + tid;
            int j = idx >> 5, kk = idx & 31;
            int kg = k0 + kk;
            int jg = n0 + j;
            bS[kk * 65 + j] = (kg < 384) ? W_ih[jg * 384 + kg] : W_hh[jg * 256 + (kg - 384)];
        }
        __syncthreads();
#pragma unroll
        for (int kk = 0; kk < 32; kk++) {
            float a[4], w[4];
#pragma unroll
            for (int i = 0; i < 4; i++) a[i] = aT[kk * 65 + ty * 4 + i];
#pragma unroll
            for (int j = 0; j < 4; j++) w[j] = bS[kk * 65 + tx * 4 + j];
#pragma unroll
            for (int i = 0; i < 4; i++)
#pragma unroll
                for (int j = 0; j < 4; j++) acc[i][j] += a[i] * w[j];
        }
    }
#pragma unroll
    for (int i = 0; i < 4; i++) {
        int row = m0 + ty * 4 + i;
#pragma unroll
        for (int j = 0; j < 4; j++) {
            int col = n0 + tx * 4 + j;
            g_gates[row * 1024 + col] = acc[i][j] + b_ih[col] + b_hh[col];
        }
    }
}

// ---------------------------------------------------------------------------
// 3) LSTM cell
// ---------------------------------------------------------------------------
__global__ void cell_kernel(const float* __restrict__ c0, float* __restrict__ out) {
    int b = blockIdx.x, d = threadIdx.x;
    const float* g = g_gates + b * 1024;
    float ig = g[d], fg = g[256 + d], gg = g[512 + d], og = g[768 + d];
    float c = sigmoidf(fg) * c0[b * HH + d] + sigmoidf(ig) * tanhf(gg);
    float h = sigmoidf(og) * tanhf(c);
    out[b * HH + d] = h;
    out[BB * HH + b * HH + d] = c;
}

// ---------------------------------------------------------------------------
// 4) hp GEMM (unchanged)
// ---------------------------------------------------------------------------
__global__ __launch_bounds__(256) void hproj_gemm_kernel(
    const float* __restrict__ W2, const float* __restrict__ out) {
    __shared__ float aT[32 * 65];
    __shared__ float bS[32 * 65];
    int n0 = blockIdx.x * 64;
    int m0 = blockIdx.y * 64;
    int tid = threadIdx.x;
    int tx = tid & 15, ty = tid >> 4;

    float acc[4][4];
#pragma unroll
    for (int i = 0; i < 4; i++)
#pragma unroll
        for (int j = 0; j < 4; j++) acc[i][j] = 0.f;

    for (int k0 = 0; k0 < HH; k0 += 32) {
        __syncthreads();
#pragma unroll
        for (int rep = 0; rep < 8; rep++) {
            int idx = rep * 256 + tid;
            int r = idx >> 5, kk = idx & 31;
            aT[kk * 65 + r] = out[(m0 + r) * HH + k0 + kk];
        }
#pragma unroll
        for (int rep = 0; rep < 8; rep++) {
            int idx = rep * 256 + tid;
            int j = idx >> 5, kk = idx & 31;
            bS[kk * 65 + j] = W2[(n0 + j) * HH + k0 + kk];
        }
        __syncthreads();
#pragma unroll
        for (int kk = 0; kk < 32; kk++) {
            float a[4], w[4];
#pragma unroll
            for (int i = 0; i < 4; i++) a[i] = aT[kk * 65 + ty * 4 + i];
#pragma unroll
            for (int j = 0; j < 4; j++) w[j] = bS[kk * 65 + tx * 4 + j];
#pragma unroll
            for (int i = 0; i < 4; i++)
#pragma unroll
                for (int j = 0; j < 4; j++) acc[i][j] += a[i] * w[j];
        }
    }
#pragma unroll
    for (int i = 0; i < 4; i++)
#pragma unroll
        for (int j = 0; j < 4; j++)
            g_hp[(m0 + ty * 4 + i) * DD + n0 + tx * 4 + j] = acc[i][j];
}

// ---------------------------------------------------------------------------
// 5) PERSISTENT attention, 512 threads, fp16 inputs + FP16 ACCUMULATORS.
// ---------------------------------------------------------------------------
__global__ __launch_bounds__(512, 1) void attn_mma_kernel(
    const float* __restrict__ enc, const float* __restrict__ beta) {
    extern __shared__ char sm[];
    float* hpS   = (float*)(sm + SM_HP);     // [2][256]
    float* betaS = (float*)(sm + SM_BETA);
    float* wS    = (float*)(sm + SM_WS);
    float* sred  = (float*)(sm + SM_SRED);
    char*  encS  = sm + SM_ENC;
    char*  w1S   = sm + SM_W1;

    int tid = threadIdx.x, wid = tid >> 5, lane = tid & 31;
    int g = lane >> 2, t = lane & 3;
    int mg = wid >> 2, ng = wid & 3;       // 4 m-groups x 4 n-groups
    int half = mg >> 1;
    int p2 = tid & 255;
    int stage_m0 = wid * 8;
    float* hpMy = hpS + half * 256;

    // W1 fp16 (K-permuted) -> smem ONCE: 8704 uint4 = 17 x 512
    {
        const uint4* src = (const uint4*)g_W1h;
        uint4* dst = (uint4*)w1S;
#pragma unroll 4
        for (int it = 0; it < 17; it++) dst[it * 512 + tid] = src[it * 512 + tid];
    }
    if (tid < 256) betaS[tid] = beta[tid];

    const int END = BB * NCH;

    // prologue: stage first tile (own 8 rows) + own-half hp copy
    {
        int tl0 = blockIdx.x;
        int b0 = tl0 >> 3, l00 = (tl0 & 7) << 7;
        const float* wrow = enc + ((size_t)b0 * LL + l00 + stage_m0) * DD;
        char* sdst = encS + stage_m0 * ROWB;
#pragma unroll 8
        for (int it = 0; it < 16; it++) {
            int idx = it * 32 + lane;
            int rl = idx >> 6;
            int c4 = idx & 63;
            float4 v = *(const float4*)(wrow + rl * DD + c4 * 4);
            __half2 p0 = __floats2half2_rn(v.x, v.y);
            __half2 p1 = __floats2half2_rn(v.z, v.w);
            int k0 = 4 * c4;
            *(uint32_t*)(sdst + rl * ROWB + kperm(k0) * 4)     = *(uint32_t*)&p0;
            *(uint32_t*)(sdst + rl * ROWB + kperm(k0 + 2) * 4) = *(uint32_t*)&p1;
        }
        hpMy[p2] = g_hp[b0 * DD + p2];
    }

    for (int tl = blockIdx.x; tl < END; tl += NSM) {
        int b = tl >> 3, ch = tl & 7, l0 = ch << 7;
        const float* encB = enc + ((size_t)b * LL + l0) * DD;

        named_bar(1 + half, 256);

        // ---- MMA mainloop: warp tile rows [mg*32,+32) x cols [ng*64,+64)
        uint32_t acc[2][8][2];
#pragma unroll
        for (int mi = 0; mi < 2; mi++)
#pragma unroll
            for (int jt = 0; jt < 8; jt++) {
                acc[mi][jt][0] = 0u;
                acc[mi][jt][1] = 0u;
            }

        const char* abase = encS + (mg * 32 + g) * ROWB + t * 8;
        const char* bbase = w1S + (ng * 64 + g) * ROWB + t * 8;
#pragma unroll
        for (int kb = 0; kb < 16; kb++) {
            uint2 alo[2], ahi[2];
#pragma unroll
            for (int mi = 0; mi < 2; mi++) {
                const char* pa = abase + mi * 16 * ROWB + kb * 32;
                alo[mi] = *(const uint2*)(pa);
                ahi[mi] = *(const uint2*)(pa + 8 * ROWB);
            }
#pragma unroll
            for (int jt = 0; jt < 8; jt++) {
                uint2 bf = *(const uint2*)(bbase + jt * 8 * ROWB + kb * 32);
#pragma unroll
                for (int mi = 0; mi < 2; mi++)
                    mma_f16(acc[mi][jt], alo[mi].x, ahi[mi].x, alo[mi].y, ahi[mi].y, bf.x, bf.y);
            }
        }

        // ---- epilogue: partial scores (unpack f16 accum -> fp32)
#pragma unroll
        for (int mi = 0; mi < 2; mi++) {
            float s0 = 0.f, s1 = 0.f;
#pragma unroll
            for (int jt = 0; jt < 8; jt++) {
                int c = ng * 64 + jt * 8 + t * 2;
                float b0 = betaS[c], b1 = betaS[c + 1];
                float h0v = hpMy[c], h1v = hpMy[c + 1];
                __half2 lo = *(__half2*)&acc[mi][jt][0];   // row g:   cols c, c+1
                __half2 hi = *(__half2*)&acc[mi][jt][1];   // row g+8: cols c, c+1
                s0 += b0 * tanh_fast(__low2float(lo) + h0v) + b1 * tanh_fast(__high2float(lo) + h1v);
                s1 += b0 * tanh_fast(__low2float(hi) + h0v) + b1 * tanh_fast(__high2float(hi) + h1v);
            }
            s0 += __shfl_xor_sync(0xffffffffu, s0, 1);
            s0 += __shfl_xor_sync(0xffffffffu, s0, 2);
            s1 += __shfl_xor_sync(0xffffffffu, s1, 1);
            s1 += __shfl_xor_sync(0xffffffffu, s1, 2);
            if (t == 0) {
                int row = mg * 32 + mi * 16 + g;
                sred[row * 5 + ng] = s0;
                sred[(row + 8) * 5 + ng] = s1;
            }
        }
        __syncthreads();   // S1: sred complete, encS/hpS free for restage

        if (tid < 128) {
            float s = sred[tid * 5] + sred[tid * 5 + 1] + sred[tid * 5 + 2] + sred[tid * 5 + 3];
            wS[tid] = expf(s);
        }
        __syncthreads();   // S2: wS complete

        if (tid < 32) {
            float ps = wS[tid] + wS[tid + 32] + wS[tid + 64] + wS[tid + 96];
#pragma unroll
            for (int o = 16; o > 0; o >>= 1) ps += __shfl_down_sync(0xffffffffu, ps, o);
            if (tid == 0) g_partS[b * NCH + ch] = ps;
        }

        // ---- FUSED TAIL: stage next tile (own rows) + context (own half)
        int tn = tl + NSM;
        if (tn < END) {
            int bn = tn >> 3, l0n = (tn & 7) << 7;
            const float* wrow = enc + ((size_t)bn * LL + l0n + stage_m0) * DD;
            char* sdst = encS + stage_m0 * ROWB;
#pragma unroll 8
            for (int it = 0; it < 16; it++) {
                int idx = it * 32 + lane;
                int rl = idx >> 6;
                int c4 = idx & 63;
                float4 v = *(const float4*)(wrow + rl * DD + c4 * 4);
                __half2 p0 = __floats2half2_rn(v.x, v.y);
                __half2 p1 = __floats2half2_rn(v.z, v.w);
                int k0 = 4 * c4;
                *(uint32_t*)(sdst + rl * ROWB + kperm(k0) * 4)     = *(uint32_t*)&p0;
                *(uint32_t*)(sdst + rl * ROWB + kperm(k0 + 2) * 4) = *(uint32_t*)&p1;
            }
            hpMy[p2] = g_hp[bn * DD + p2];
        }

        // context: own half rows (64), one column per thread, fp32 from gmem
        {
            float C = 0.f;
            const float* base = encB + (half * 64) * DD + p2;
            const float* wHalf = wS + half * 64;
#pragma unroll 8
            for (int r = 0; r < 64; r++) C += wHalf[r] * base[r * DD];
            g_partC[((size_t)(b * NCH + ch) * 2 + half) * DD + p2] = C;
        }
    }
}

// ---------------------------------------------------------------------------
// 6) context = sum(partC halves) / sum(partS)
// ---------------------------------------------------------------------------
__global__ void ctx_reduce_kernel() {
    int b = blockIdx.x, d = threadIdx.x;
    float S = 0.f, C = 0.f;
#pragma unroll
    for (int c = 0; c < NCH; c++) {
        S += g_partS[b * NCH + c];
        C += g_partC[((b * NCH + c) * 2) * DD + d] + g_partC[((b * NCH + c) * 2 + 1) * DD + d];
    }
    g_ctx[b * DD + d] = C / S;
}

// ---------------------------------------------------------------------------
// 7) o_new GEMM (unchanged)
// ---------------------------------------------------------------------------
__global__ __launch_bounds__(256) void onew_gemm_kernel(
    const float* __restrict__ W3, float* __restrict__ out) {
    __shared__ float aT[32 * 65];
    __shared__ float bS[32 * 65];
    int n0 = blockIdx.x * 64;
    int m0 = blockIdx.y * 64;
    int tid = threadIdx.x;
    int tx = tid & 15, ty = tid >> 4;

    float acc[4][4];
#pragma unroll
    for (int i = 0; i < 4; i++)
#pragma unroll
        for (int j = 0; j < 4; j++) acc[i][j] = 0.f;

    for (int k0 = 0; k0 < 512; k0 += 32) {
        __syncthreads();
#pragma unroll
        for (int rep = 0; rep < 8; rep++) {
            int idx = rep * 256 + tid;
            int r = idx >> 5, kk = idx & 31;
            int kg = k0 + kk;
            aT[kk * 65 + r] = (kg < 256) ? out[(m0 + r) * HH + kg]
                                         : g_ctx[(m0 + r) * DD + (kg - 256)];
        }
#pragma unroll
        for (int rep = 0; rep < 8; rep++) {
            int idx = rep * 256 + tid;
            int j = idx >> 5, kk = idx & 31;
            bS[kk * 65 + j] = W3[(n0 + j) * 512 + k0 + kk];
        }
        __syncthreads();
#pragma unroll
        for (int kk = 0; kk < 32; kk++) {
            float a[4], w[4];
#pragma unroll
            for (int i = 0; i < 4; i++) a[i] = aT[kk * 65 + ty * 4 + i];
#pragma unroll
            for (int j = 0; j < 4; j++) w[j] = bS[kk * 65 + tx * 4 + j];
#pragma unroll
            for (int i = 0; i < 4; i++)
#pragma unroll
                for (int j = 0; j < 4; j++) acc[i][j] += a[i] * w[j];
        }
    }
#pragma unroll
    for (int i = 0; i < 4; i++)
#pragma unroll
        for (int j = 0; j < 4; j++)
            out[2 * BB * HH + (m0 + ty * 4 + i) * HH + n0 + tx * 4 + j] = tanhf(acc[i][j]);
}

// ---------------------------------------------------------------------------
// 8) logits GEMM (unchanged)
// ---------------------------------------------------------------------------
__global__ __launch_bounds__(256) void logit_gemm_kernel(
    const float* __restrict__ Wout, const float* __restrict__ out) {
    __shared__ float aT[32 * 65];
    __shared__ float bS[32 * 65];
    int n0 = blockIdx.x * 64;
    int m0 = blockIdx.y * 64;
    int tid = threadIdx.x;
    int tx = tid & 15, ty = tid >> 4;
    const float* onew = out + 2 * BB * HH;

    float acc[4][4];
#pragma unroll
    for (int i = 0; i < 4; i++)
#pragma unroll
        for (int j = 0; j < 4; j++) acc[i][j] = 0.f;

    for (int k0 = 0; k0 < HH; k0 += 32) {
        __syncthreads();
#pragma unroll
        for (int rep = 0; rep < 8; rep++) {
            int idx = rep * 256 + tid;
            int r = idx >> 5, kk = idx & 31;
            aT[kk * 65 + r] = onew[(m0 + r) * HH + k0 + kk];
        }
#pragma unroll
        for (int rep = 0; rep < 8; rep++) {
            int idx = rep * 256 + tid;
            int j = idx >> 5, kk = idx & 31;
            int jg = n0 + j;
            bS[kk * 65 + j] = (jg < NOUT) ? Wout[jg * HH + k0 + kk] : 0.f;
        }
        __syncthreads();
#pragma unroll
        for (int kk = 0; kk < 32; kk++) {
            float a[4], w[4];
#pragma unroll
            for (int i = 0; i < 4; i++) a[i] = aT[kk * 65 + ty * 4 + i];
#pragma unroll
            for (int j = 0; j < 4; j++) w[j] = bS[kk * 65 + tx * 4 + j];
#pragma unroll
            for (int i = 0; i < 4; i++)
#pragma unroll
                for (int j = 0; j < 4; j++) acc[i][j] += a[i] * w[j];
        }
    }
#pragma unroll
    for (int i = 0; i < 4; i++) {
        int row = m0 + ty * 4 + i;
#pragma unroll
        for (int j = 0; j < 4; j++) {
            int col = n0 + tx * 4 + j;
            if (col < NOUT) g_logits[row * NOUT + col] = acc[i][j];
        }
    }
}

// ---------------------------------------------------------------------------
// 9) logit softmax
// ---------------------------------------------------------------------------
__global__ void softmax_logit_kernel(float* __restrict__ out) {
    __shared__ float lg[NOUT];
    __shared__ float red;
    int b = blockIdx.x, t = threadIdx.x;
    if (t < NOUT) lg[t] = g_logits[b * NOUT + t];
    __syncthreads();
    if (t == 0) {
        float m = lg[0];
        for (int i = 1; i < NOUT; i++) m = fmaxf(m, lg[i]);
        red = m;
    }
    __syncthreads();
    float e = (t < NOUT) ? expf(lg[t] - red) : 0.f;
    __syncthreads();
    if (t < NOUT) lg[t] = e;
    __syncthreads();
    if (t == 0) {
        float s = 0.f;
        for (int i = 0; i < NOUT; i++) s += lg[i];
        red = s;
    }
    __syncthreads();
    if (t < NOUT) out[3 * BB * HH + b * NOUT + t] = lg[t] / red;
}

// ---------------------------------------------------------------------------
extern "C" void kernel_launch(void* const* d_in, const int* in_sizes, int n_in,
                              void* d_out, int out_size) {
    const float* h0      = (const float*)d_in[0];
    const float* c0      = (const float*)d_in[1];
    const float* o_t     = (const float*)d_in[2];
    const float* enc_out = (const float*)d_in[3];
    const int*   lt      = (const int*)  d_in[4];
    const float* emb     = (const float*)d_in[5];
    const float* W_ih    = (const float*)d_in[6];
    const float* W_hh    = (const float*)d_in[7];
    const float* b_ih    = (const float*)d_in[8];
    const float* b_hh    = (const float*)d_in[9];
    const float* W1      = (const float*)d_in[10];
    const float* W2      = (const float*)d_in[11];
    const float* W3      = (const float*)d_in[12];
    const float* W_out   = (const float*)d_in[13];
    const float* beta    = (const float*)d_in[14];
    float* out = (float*)d_out;

    cudaFuncSetAttribute(attn_mma_kernel, cudaFuncAttributeMaxDynamicSharedMemorySize, SM_TOTAL);

    prep_A_kernel<<<BB, KIN>>>(emb, lt, o_t, h0);
    prep_W1_kernel<<<256, 128>>>(W1);
    gates_gemm_kernel<<<dim3(16, 4), 256>>>(W_ih, W_hh, b_ih, b_hh);
    cell_kernel<<<BB, HH>>>(c0, out);
    hproj_gemm_kernel<<<dim3(4, 4), 256>>>(W2, out);
    attn_mma_kernel<<<NSM, 512, SM_TOTAL>>>(enc_out, beta);
    ctx_reduce_kernel<<<BB, DD>>>();
    onew_gemm_kernel<<<dim3(4, 4), 256>>>(W3, out);
    logit_gemm_kernel<<<dim3(3, 4), 256>>>(W_out, out);
    softmax_logit_kernel<<<BB, 192>>>(out);
}